// round 3
// baseline (speedup 1.0000x reference)
#include <cuda_runtime.h>
#include <mma.h>
#include <cstdint>

using namespace nvcuda;

#define H 1024
#define BZd 256
#define NKEYS 131072
#define NU 7
#define SMEM_FLOATS 27584
#define SMEM_BYTES (SMEM_FLOATS * 4)

__constant__ int c_ud[NU]   = {256, 256, 128, 128, 128, 64, 64};
__constant__ int c_uoff[NU] = {0, 256, 512, 640, 768, 896, 960};

__device__ float g_qrot[BZd * H];
__device__ float g_qhat[BZd * H];
__device__ unsigned long long g_best[NU * BZd];
__device__ float g_cos[NU * BZd];

// ------------------------------------------------------------------
// K1a: qrot = query @ R   (fp32 FFMA, exact)
// grid 32, block 256; each CTA does 8 rows of qrot
// ------------------------------------------------------------------
__global__ void qrot_kernel(const float* __restrict__ q, const float* __restrict__ R) {
    __shared__ float sq[8 * H];
    const int b0 = blockIdx.x * 8;
    const int t = threadIdx.x;
    for (int i = t; i < 8 * H; i += 256) sq[i] = q[(size_t)b0 * H + i];
    __syncthreads();
    float acc[8][4] = {};
    for (int i = 0; i < H; ++i) {
        const float* Rr = R + (size_t)i * H;
        float r0 = Rr[t];
        float r1 = Rr[t + 256];
        float r2 = Rr[t + 512];
        float r3 = Rr[t + 768];
#pragma unroll
        for (int bb = 0; bb < 8; ++bb) {
            float qv = sq[bb * H + i];
            acc[bb][0] += qv * r0;
            acc[bb][1] += qv * r1;
            acc[bb][2] += qv * r2;
            acc[bb][3] += qv * r3;
        }
    }
#pragma unroll
    for (int bb = 0; bb < 8; ++bb)
#pragma unroll
        for (int jj = 0; jj < 4; ++jj)
            g_qrot[(size_t)(b0 + bb) * H + t + jj * 256] = acc[bb][jj];
}

// ------------------------------------------------------------------
// K1b: per-unit normalize qrot -> g_qhat; init g_best
// grid 256 (one per b), block 256
// ------------------------------------------------------------------
__global__ void qhat_kernel() {
    __shared__ float sx[H];
    __shared__ float sred[256];
    const int b = blockIdx.x, t = threadIdx.x;
    for (int i = t; i < H; i += 256) sx[i] = g_qrot[(size_t)b * H + i];
    if (b == 0) {
        // packed(-2.0f, idx=0): ordered bits of -2.0f = ~0xC0000000 = 0x3FFFFFFF
        for (int k = t; k < NU * BZd; k += 256) g_best[k] = 0x3FFFFFFF00000000ULL;
    }
    __syncthreads();
    for (int u = 0; u < NU; ++u) {
        const int d = c_ud[u], off = c_uoff[u];
        float s = 0.0f;
        for (int c = t; c < d; c += 256) { float v = sx[off + c]; s += v * v; }
        sred[t] = s;
        __syncthreads();
        for (int w = 128; w > 0; w >>= 1) {
            if (t < w) sred[t] += sred[t + w];
            __syncthreads();
        }
        float inv = 1.0f / fmaxf(sqrtf(sred[0]), 1e-8f);
        __syncthreads();  // everyone has read sred[0]
        for (int c = t; c < d; c += 256) g_qhat[(size_t)b * H + off + c] = sx[off + c] * inv;
    }
}

// ------------------------------------------------------------------
// K2: main scan kernel (tf32 wmma)
// grid 2048 (64 keys each), block 256 (8 warps)
// ------------------------------------------------------------------
typedef wmma::fragment<wmma::matrix_a, 16, 16, 8, wmma::precision::tf32, wmma::row_major> FragA;
typedef wmma::fragment<wmma::matrix_b, 16, 16, 8, wmma::precision::tf32, wmma::row_major> FragBr;
typedef wmma::fragment<wmma::matrix_b, 16, 16, 8, wmma::precision::tf32, wmma::col_major> FragBc;
typedef wmma::fragment<wmma::accumulator, 16, 16, 8, float> FragC;

// sim accumulation: sims[b(256) x l(64)] += Qhat[b, qoff_g:+Kp] * Krot[l, colbase:+Kp]^T
__device__ __forceinline__ void gemm2_accum(FragC (&cS)[4][2], float* sQ, const float* sKrot,
                                            int qoff_g, int colbase, int Kp,
                                            int t, int wm2, int wn2) {
    for (int ck = 0; ck < Kp; ck += 32) {
        __syncthreads();
#pragma unroll
        for (int r = 0; r < 8; ++r) {
            int id = t + r * 256;
            int row = id >> 3, c4 = (id & 7) * 4;
            *(float4*)(sQ + row * 40 + c4) =
                *(const float4*)(g_qhat + (size_t)row * H + qoff_g + ck + c4);
        }
        __syncthreads();
#pragma unroll
        for (int k8 = 0; k8 < 4; ++k8) {
            FragA a[4];
            FragBc bf[2];
#pragma unroll
            for (int i = 0; i < 4; ++i) {
                wmma::load_matrix_sync(a[i], sQ + (size_t)(wm2 * 64 + 16 * i) * 40 + k8 * 8, 40);
                for (int e = 0; e < a[i].num_elements; ++e)
                    a[i].x[e] = wmma::__float_to_tf32(a[i].x[e]);
            }
#pragma unroll
            for (int j = 0; j < 2; ++j) {
                wmma::load_matrix_sync(bf[j],
                    sKrot + (size_t)(wn2 * 32 + 16 * j) * 136 + colbase + ck + k8 * 8, 136);
                for (int e = 0; e < bf[j].num_elements; ++e)
                    bf[j].x[e] = wmma::__float_to_tf32(bf[j].x[e]);
            }
#pragma unroll
            for (int i = 0; i < 4; ++i)
#pragma unroll
                for (int j = 0; j < 2; ++j)
                    wmma::mma_sync(cS[i][j], a[i], bf[j], cS[i][j]);
        }
    }
}

__device__ __forceinline__ void finalize_unit(FragC (&cS)[4][2], float* sSim,
                                              const float* sNorm2, float* sRN,
                                              int u, int slot, int L0,
                                              int t, int wm2, int wn2) {
    __syncthreads();  // all warps done with GEMM2 (sQ aliases sSim)
#pragma unroll
    for (int i = 0; i < 4; ++i)
#pragma unroll
        for (int j = 0; j < 2; ++j) {
            wmma::store_matrix_sync(sSim + (size_t)(wm2 * 64 + 16 * i) * 72 + wn2 * 32 + 16 * j,
                                    cS[i][j], 72, wmma::mem_row_major);
            wmma::fill_fragment(cS[i][j], 0.0f);
        }
    __syncthreads();
    if (t < 64) sRN[t] = 1.0f / fmaxf(sqrtf(sNorm2[slot * 64 + t]), 1e-3f);
    __syncthreads();
    {
        float best = -1e30f;
        int bi = 0;
        const float* srow = sSim + (size_t)t * 72;
#pragma unroll 8
        for (int l = 0; l < 64; ++l) {
            float v = srow[l] * sRN[l];
            if (v > best) { best = v; bi = l; }  // strict > => first index on ties
        }
        unsigned vb = __float_as_uint(best);
        vb = (vb & 0x80000000u) ? ~vb : (vb | 0x80000000u);
        unsigned long long pk = ((unsigned long long)vb << 32) |
                                (unsigned long long)(0xFFFFFFFFu - (unsigned)(L0 + bi));
        atomicMax(&g_best[u * BZd + t], pk);
    }
}

__global__ void __launch_bounds__(256, 1)
scan_kernel(const float* __restrict__ keys, const float* __restrict__ R) {
    extern __shared__ float sm[];
    float* sKrot  = sm;                       // 64 x 136 = 8704
    float* sX     = sm + 8704;                // aliased region, 18432 floats
    float* sA     = sX;                       // 64 x 40
    float* sB     = sX + 2560;                // 32 x 136
    float* sQ     = sX + 6912;                // 256 x 40
    float* sSim   = sX;                       // 256 x 72 (alias)
    float* sPart  = sm + 8704 + 18432;        // 256
    float* sNorm2 = sPart + 256;              // 128 (2 slots x 64)
    float* sRN    = sNorm2 + 128;             // 64

    const int t = threadIdx.x;
    const int warpId = t >> 5;
    const int L0 = blockIdx.x * 64;
    const int wm = warpId & 1, wn = warpId >> 1;    // GEMM1: 2(M) x 4(N)
    const int wm2 = warpId & 3, wn2 = warpId >> 2;  // GEMM2: 4(M) x 2(N)

    FragC cS[4][2];
#pragma unroll
    for (int i = 0; i < 4; ++i)
#pragma unroll
        for (int j = 0; j < 2; ++j) wmma::fill_fragment(cS[i][j], 0.0f);

    for (int p = 0; p < 8; ++p) {
        const int coff = p * 128;
        FragC cK[2][2];
#pragma unroll
        for (int i = 0; i < 2; ++i)
#pragma unroll
            for (int j = 0; j < 2; ++j) wmma::fill_fragment(cK[i][j], 0.0f);

        // ---------- GEMM1: Krot_panel[64,128] = K[64,1024] @ R[:,coff:coff+128]
        for (int kk = 0; kk < H; kk += 32) {
            __syncthreads();
#pragma unroll
            for (int r = 0; r < 2; ++r) {
                int id = t + r * 256;
                int row = id >> 3, c4 = (id & 7) * 4;
                *(float4*)(sA + row * 40 + c4) =
                    *(const float4*)(keys + (size_t)(L0 + row) * H + kk + c4);
            }
#pragma unroll
            for (int r = 0; r < 4; ++r) {
                int id = t + r * 256;
                int row = id >> 5, c4 = (id & 31) * 4;
                *(float4*)(sB + row * 136 + c4) =
                    *(const float4*)(R + (size_t)(kk + row) * H + coff + c4);
            }
            __syncthreads();
#pragma unroll
            for (int k8 = 0; k8 < 4; ++k8) {
                FragA a[2];
                FragBr bf[2];
#pragma unroll
                for (int i = 0; i < 2; ++i) {
                    wmma::load_matrix_sync(a[i], sA + (size_t)(wm * 32 + 16 * i) * 40 + k8 * 8, 40);
                    for (int e = 0; e < a[i].num_elements; ++e)
                        a[i].x[e] = wmma::__float_to_tf32(a[i].x[e]);
                }
#pragma unroll
                for (int j = 0; j < 2; ++j) {
                    wmma::load_matrix_sync(bf[j], sB + (size_t)(k8 * 8) * 136 + wn * 32 + 16 * j, 136);
                    for (int e = 0; e < bf[j].num_elements; ++e)
                        bf[j].x[e] = wmma::__float_to_tf32(bf[j].x[e]);
                }
#pragma unroll
                for (int i = 0; i < 2; ++i)
#pragma unroll
                    for (int j = 0; j < 2; ++j)
                        wmma::mma_sync(cK[i][j], a[i], bf[j], cK[i][j]);
            }
        }
        __syncthreads();
#pragma unroll
        for (int i = 0; i < 2; ++i)
#pragma unroll
            for (int j = 0; j < 2; ++j)
                wmma::store_matrix_sync(sKrot + (size_t)(wm * 32 + 16 * i) * 136 + wn * 32 + 16 * j,
                                        cK[i][j], 136, wmma::mem_row_major);
        __syncthreads();

        // ---------- norms (fp32 from Krot panel)
        {
            int l = t & 63, q = t >> 6;
            const float* row = sKrot + (size_t)l * 136 + q * 32;
            float s = 0.0f;
#pragma unroll
            for (int i = 0; i < 32; ++i) s += row[i] * row[i];
            sPart[t] = s;
        }
        __syncthreads();
        if (t < 64) {
            if (p < 7) {
                float s = sPart[t] + sPart[t + 64] + sPart[t + 128] + sPart[t + 192];
                bool first = (p == 0) | (p == 2) | (p == 4) | (p == 5) | (p == 6);
                sNorm2[t] = first ? s : (sNorm2[t] + s);
            } else {
                sNorm2[t] = sPart[t] + sPart[t + 64];
                sNorm2[t + 64] = sPart[t + 128] + sPart[t + 192];
            }
        }

        // ---------- GEMM2 + finalize
        if (p < 7) {
            const int u = (p < 2) ? 0 : (p < 4) ? 1 : (p - 2);
            gemm2_accum(cS, sQ, sKrot, coff, 0, 128, t, wm2, wn2);
            bool last = (p == 1) | (p == 3) | (p >= 4);
            if (last) finalize_unit(cS, sSim, sNorm2, sRN, u, 0, L0, t, wm2, wn2);
        } else {
#pragma unroll
            for (int h = 0; h < 2; ++h) {
                gemm2_accum(cS, sQ, sKrot, 896 + h * 64, h * 64, 64, t, wm2, wn2);
                finalize_unit(cS, sSim, sNorm2, sRN, 5 + h, h, L0, t, wm2, wn2);
            }
        }
    }
}

// ------------------------------------------------------------------
// K3: gather winners, exact fp32 diag + cosine
// grid 1792 (u = blk/256, b = blk%256), block 256
// ------------------------------------------------------------------
__global__ void final_kernel(const float* __restrict__ keys, const float* __restrict__ R) {
    __shared__ float sv[H];
    __shared__ float sred[256];
    const int u = blockIdx.x >> 8;
    const int b = blockIdx.x & 255;
    const int t = threadIdx.x;
    unsigned long long pk = g_best[u * BZd + b];
    unsigned idx = 0xFFFFFFFFu - (unsigned)(pk & 0xFFFFFFFFull);
    const float* v = keys + (size_t)idx * H;
    for (int i = t; i < H; i += 256) sv[i] = v[i];
    __syncthreads();
    const int d = c_ud[u], off = c_uoff[u];
    float dg = 0.0f, qc = 0.0f;
    if (t < d) {
        const float* Rc = R + off + t;
#pragma unroll 4
        for (int i = 0; i < H; ++i) dg += sv[i] * Rc[(size_t)i * H];
        qc = g_qrot[(size_t)b * H + off + t];
    }
    float num = qc * dg, nd = dg * dg, nq = qc * qc;
    float tot[3];
    float vals[3] = {num, nd, nq};
#pragma unroll
    for (int r = 0; r < 3; ++r) {
        sred[t] = vals[r];
        __syncthreads();
        for (int w = 128; w > 0; w >>= 1) {
            if (t < w) sred[t] += sred[t + w];
            __syncthreads();
        }
        tot[r] = sred[0];
        __syncthreads();
    }
    if (t == 0) {
        float cosv = tot[0] / (fmaxf(sqrtf(tot[2]), 1e-8f) * fmaxf(sqrtf(tot[1]), 1e-8f));
        g_cos[u * BZd + b] = cosv * (float)d;
    }
}

// ------------------------------------------------------------------
// K4: deterministic ordered reduction to scalar
// ------------------------------------------------------------------
__global__ void reduce_kernel(float* __restrict__ out) {
    __shared__ float sred[256];
    const int t = threadIdx.x;
    float s = 0.0f;
    for (int k = t; k < NU * BZd; k += 256) s += g_cos[k];
    sred[t] = s;
    __syncthreads();
    for (int w = 128; w > 0; w >>= 1) {
        if (t < w) sred[t] += sred[t + w];
        __syncthreads();
    }
    if (t == 0) out[0] = -sred[0] / (float)(BZd * H) * (float)BZd / (float)BZd; // = -sum/(256*1024)
}

// ------------------------------------------------------------------
extern "C" void kernel_launch(void* const* d_in, const int* in_sizes, int n_in,
                              void* d_out, int out_size) {
    const float* query = nullptr;
    const float* keys = nullptr;
    const float* R = nullptr;
    for (int i = 0; i < n_in; ++i) {
        if (in_sizes[i] == BZd * H) query = (const float*)d_in[i];
        else if (in_sizes[i] == NKEYS * H) keys = (const float*)d_in[i];
        else if (in_sizes[i] == H * H) R = (const float*)d_in[i];
    }
    if (!query) query = (const float*)d_in[0];
    if (!keys) keys = (const float*)d_in[1];
    if (!R) R = (const float*)d_in[2];
    float* out = (float*)d_out;

    cudaFuncSetAttribute(scan_kernel, cudaFuncAttributeMaxDynamicSharedMemorySize, SMEM_BYTES);

    qrot_kernel<<<32, 256>>>(query, R);
    qhat_kernel<<<256, 256>>>();
    scan_kernel<<<NKEYS / 64, 256, SMEM_BYTES>>>(keys, R);
    final_kernel<<<NU * BZd, 256>>>(keys, R);
    reduce_kernel<<<1, 256>>>(out);
}

// round 5
// speedup vs baseline: 1.8838x; 1.8838x over previous
#include <cuda_runtime.h>
#include <cstdint>

#define H 1024
#define BZd 256
#define NKEYS 131072
#define NU 7

__constant__ int c_ud[NU]   = {256, 256, 128, 128, 128, 64, 64};
__constant__ int c_uoff[NU] = {0, 256, 512, 640, 768, 896, 960};

__device__ float g_qrot[BZd * H];
__device__ float g_qhat[BZd * H];
__device__ unsigned long long g_best[NU * BZd];
__device__ float g_cos[NU * BZd];

// ---------------- smem layout (float offsets) ----------------
#define OF_KA 0                       // Krot panel A [128][132]
#define OF_KB 16896                   // Krot panel B [128][132]
#define OF_A(b) (33792 + (b) * 4608)  // GEMM1 A stage [128][36] x2
#define OF_B(b) (43008 + (b) * 4352)  // GEMM1 B stage [32][136] x2
#define OF_Q(b) (33792 + (b) * 5120)  // GEMM2 Q stage [256][20] x2 (aliases A/B stages)
#define OF_PART 51712                 // 256 floats
#define OF_RN 51968                   // 128 floats
#define OF_WMAX 52096                 // 512 u64 (8B aligned: 52096*4 = 208384)
#define SMEM_FLOATS 53120
#define SMEM_BYTES (SMEM_FLOATS * 4)  // 212480

// ---------------- PTX helpers ----------------
#define CPA16(dst, src) \
    asm volatile("cp.async.cg.shared.global [%0], [%1], 16;" :: "r"(dst), "l"(src))
#define CPCOMMIT asm volatile("cp.async.commit_group;" ::: "memory")
#define CPWAIT1 asm volatile("cp.async.wait_group 1;" ::: "memory")
#define CPWAIT0 asm volatile("cp.async.wait_group 0;" ::: "memory")

__device__ __forceinline__ void mma8(float* d, const uint32_t* a, const uint32_t* b) {
    asm volatile(
        "mma.sync.aligned.m16n8k8.row.col.f32.tf32.tf32.f32 "
        "{%0,%1,%2,%3},{%4,%5,%6,%7},{%8,%9},{%0,%1,%2,%3};"
        : "+f"(d[0]), "+f"(d[1]), "+f"(d[2]), "+f"(d[3])
        : "r"(a[0]), "r"(a[1]), "r"(a[2]), "r"(a[3]), "r"(b[0]), "r"(b[1]));
}

__device__ __forceinline__ uint32_t fbits(float f) { return __float_as_uint(f); }

__device__ __forceinline__ unsigned long long umax64(unsigned long long a,
                                                     unsigned long long b) {
    return a > b ? a : b;
}

// ================= K1a: qrot = query @ R (exact fp32) =================
__global__ void qrot_kernel(const float* __restrict__ q, const float* __restrict__ R) {
    __shared__ float sq[8 * H];
    const int b0 = blockIdx.x * 8;
    const int t = threadIdx.x;
    for (int i = t; i < 8 * H; i += 256) sq[i] = q[(size_t)b0 * H + i];
    __syncthreads();
    float acc[8][4] = {};
    for (int i = 0; i < H; ++i) {
        const float* Rr = R + (size_t)i * H;
        float r0 = Rr[t], r1 = Rr[t + 256], r2 = Rr[t + 512], r3 = Rr[t + 768];
#pragma unroll
        for (int bb = 0; bb < 8; ++bb) {
            float qv = sq[bb * H + i];
            acc[bb][0] += qv * r0; acc[bb][1] += qv * r1;
            acc[bb][2] += qv * r2; acc[bb][3] += qv * r3;
        }
    }
#pragma unroll
    for (int bb = 0; bb < 8; ++bb)
#pragma unroll
        for (int jj = 0; jj < 4; ++jj)
            g_qrot[(size_t)(b0 + bb) * H + t + jj * 256] = acc[bb][jj];
}

// ================= K1b: per-unit normalize; init g_best =================
__global__ void qhat_kernel() {
    __shared__ float sx[H];
    __shared__ float sred[256];
    const int b = blockIdx.x, t = threadIdx.x;
    for (int i = t; i < H; i += 256) sx[i] = g_qrot[(size_t)b * H + i];
    if (b == 0) {
        for (int k = t; k < NU * BZd; k += 256) g_best[k] = 0x3FFFFFFF00000000ULL;
    }
    __syncthreads();
    for (int u = 0; u < NU; ++u) {
        const int d = c_ud[u], off = c_uoff[u];
        float s = 0.0f;
        for (int c = t; c < d; c += 256) { float v = sx[off + c]; s += v * v; }
        sred[t] = s;
        __syncthreads();
        for (int w = 128; w > 0; w >>= 1) {
            if (t < w) sred[t] += sred[t + w];
            __syncthreads();
        }
        float inv = 1.0f / fmaxf(sqrtf(sred[0]), 1e-8f);
        __syncthreads();
        for (int c = t; c < d; c += 256) g_qhat[(size_t)b * H + off + c] = sx[off + c] * inv;
    }
}

// ================= K2: scan (mma.sync tf32) =================
// grid 1024 x 128 keys, block 256 (8 warps)
struct ScanCtx {
    float* sm;
    uint32_t sb4;  // smem byte base for cp.async
    const float* keys;
    const float* R;
    int t, lane, w, L0;
    int m0g1, n0g1, m0g2, n0g2;
};

__device__ __forceinline__ void stage_g1(const ScanCtx& cx, int p, int kk, int buf) {
    // A: keys[128 x 32]
    {
        const int row = cx.t >> 1, half = cx.t & 1;
        const float* src = cx.keys + (size_t)(cx.L0 + row) * H + kk * 32 + half * 16;
        const uint32_t dst = cx.sb4 + (OF_A(buf) + row * 36 + half * 16) * 4;
#pragma unroll
        for (int i = 0; i < 4; ++i) CPA16(dst + i * 16, src + i * 4);
    }
    // B: R[32 x 128] (row-major [k][n] = natural MMA B layout)
    {
        const int row = cx.t >> 3, seg = cx.t & 7;
        const float* src = cx.R + (size_t)(kk * 32 + row) * H + p * 128 + seg * 16;
        const uint32_t dst = cx.sb4 + (OF_B(buf) + row * 136 + seg * 16) * 4;
#pragma unroll
        for (int i = 0; i < 4; ++i) CPA16(dst + i * 16, src + i * 4);
    }
}

__device__ __forceinline__ void g1_panel(const ScanCtx& cx, int p, int kdst) {
    float acc1[2][8][4] = {};
    stage_g1(cx, p, 0, 0);
    CPCOMMIT;
    for (int kk = 0; kk < 32; ++kk) {
        if (kk < 31) { stage_g1(cx, p, kk + 1, (kk + 1) & 1); CPCOMMIT; CPWAIT1; }
        else { CPWAIT0; }
        __syncthreads();
        const float* bA = cx.sm + OF_A(kk & 1);
        const float* bB = cx.sm + OF_B(kk & 1);
#pragma unroll
        for (int k8 = 0; k8 < 4; ++k8) {
            const int c = k8 * 8 + (cx.lane & 3);
            uint32_t a[2][4];
#pragma unroll
            for (int i = 0; i < 2; ++i) {
                const int r = cx.m0g1 + 16 * i + (cx.lane >> 2);
                a[i][0] = fbits(bA[r * 36 + c]);
                a[i][1] = fbits(bA[(r + 8) * 36 + c]);
                a[i][2] = fbits(bA[r * 36 + c + 4]);
                a[i][3] = fbits(bA[(r + 8) * 36 + c + 4]);
            }
#pragma unroll
            for (int j = 0; j < 8; ++j) {
                const int n = cx.n0g1 + 8 * j + (cx.lane >> 2);
                uint32_t b[2];
                b[0] = fbits(bB[c * 136 + n]);
                b[1] = fbits(bB[(c + 4) * 136 + n]);
                mma8(acc1[0][j], a[0], b);
                mma8(acc1[1][j], a[1], b);
            }
        }
        __syncthreads();
    }
    float* Kd = cx.sm + kdst;
#pragma unroll
    for (int i = 0; i < 2; ++i)
#pragma unroll
        for (int j = 0; j < 8; ++j) {
            const int row = cx.m0g1 + 16 * i + (cx.lane >> 2);
            const int col = cx.n0g1 + 8 * j + (cx.lane & 3) * 2;
            *(float2*)&Kd[row * 132 + col] = make_float2(acc1[i][j][0], acc1[i][j][1]);
            *(float2*)&Kd[(row + 8) * 132 + col] = make_float2(acc1[i][j][2], acc1[i][j][3]);
        }
    __syncthreads();
}

__device__ __forceinline__ void norms(const ScanCtx& cx, int W, int cb) {
    const int key = cx.t & 127, h = cx.t >> 7;
    const int c0 = cb + h * (W / 2);
    const float* rowp = (c0 < 128) ? (cx.sm + OF_KA + key * 132 + c0)
                                   : (cx.sm + OF_KB + key * 132 + (c0 - 128));
    float s = 0.0f;
#pragma unroll 8
    for (int c = 0; c < W / 2; ++c) { float v = rowp[c]; s += v * v; }
    cx.sm[OF_PART + cx.t] = s;
    __syncthreads();
    if (cx.t < 128) {
        float tot = cx.sm[OF_PART + cx.t] + cx.sm[OF_PART + cx.t + 128];
        cx.sm[OF_RN + cx.t] = 1.0f / fmaxf(sqrtf(tot), 1e-3f);
    }
    __syncthreads();
}

__device__ __forceinline__ void stage_q(const ScanCtx& cx, int qcol0, int buf) {
    const float* src = g_qhat + (size_t)cx.t * H + qcol0;
    const uint32_t dst = cx.sb4 + (OF_Q(buf) + cx.t * 20) * 4;
#pragma unroll
    for (int i = 0; i < 4; ++i) CPA16(dst + i * 16, src + i * 4);
}

__device__ __forceinline__ void g2_resolve(const ScanCtx& cx, int u, int d, int qoff, int cb) {
    float acc2[4][8][4] = {};
    const int nch = d >> 4;
    stage_q(cx, qoff, 0);
    CPCOMMIT;
    for (int kc = 0; kc < nch; ++kc) {
        if (kc + 1 < nch) { stage_q(cx, qoff + (kc + 1) * 16, (kc + 1) & 1); CPCOMMIT; CPWAIT1; }
        else { CPWAIT0; }
        __syncthreads();
        const float* bQ = cx.sm + OF_Q(kc & 1);
        const int k0 = kc * 16;
        const float* bK;
        if (d == 256) bK = (k0 < 128) ? (cx.sm + OF_KA + k0) : (cx.sm + OF_KB + (k0 - 128));
        else bK = cx.sm + OF_KA + cb + k0;
#pragma unroll
        for (int k8 = 0; k8 < 2; ++k8) {
            const int c = k8 * 8 + (cx.lane & 3);
            uint32_t a[4][4];
#pragma unroll
            for (int i = 0; i < 4; ++i) {
                const int r = cx.m0g2 + 16 * i + (cx.lane >> 2);
                a[i][0] = fbits(bQ[r * 20 + c]);
                a[i][1] = fbits(bQ[(r + 8) * 20 + c]);
                a[i][2] = fbits(bQ[r * 20 + c + 4]);
                a[i][3] = fbits(bQ[(r + 8) * 20 + c + 4]);
            }
#pragma unroll
            for (int j = 0; j < 8; ++j) {
                const int n = cx.n0g2 + 8 * j + (cx.lane >> 2);
                uint32_t b[2];
                b[0] = fbits(bK[n * 132 + c]);
                b[1] = fbits(bK[n * 132 + c + 4]);
#pragma unroll
                for (int i = 0; i < 4; ++i) mma8(acc2[i][j], a[i], b);
            }
        }
        __syncthreads();
    }
    // resolve
    float rk[8][2];
#pragma unroll
    for (int j = 0; j < 8; ++j) {
        const int kl = cx.n0g2 + 8 * j + (cx.lane & 3) * 2;
        rk[j][0] = cx.sm[OF_RN + kl];
        rk[j][1] = cx.sm[OF_RN + kl + 1];
    }
    unsigned long long* wmax = (unsigned long long*)(cx.sm + OF_WMAX);
#pragma unroll
    for (int i = 0; i < 4; ++i)
#pragma unroll
        for (int hh = 0; hh < 2; ++hh) {
            const int q = cx.m0g2 + 16 * i + (cx.lane >> 2) + 8 * hh;
            unsigned long long best = 0ULL;
#pragma unroll
            for (int j = 0; j < 8; ++j)
#pragma unroll
                for (int e = 0; e < 2; ++e) {
                    float v = acc2[i][j][hh * 2 + e] * rk[j][e];
                    unsigned uv = __float_as_uint(v);
                    uv = (uv & 0x80000000u) ? ~uv : (uv | 0x80000000u);
                    const int kg = cx.L0 + cx.n0g2 + 8 * j + (cx.lane & 3) * 2 + e;
                    unsigned long long pk = ((unsigned long long)uv << 32) |
                                            (unsigned long long)(0xFFFFFFFFu - (unsigned)kg);
                    best = umax64(best, pk);
                }
            best = umax64(best, __shfl_xor_sync(0xFFFFFFFFu, best, 1));
            best = umax64(best, __shfl_xor_sync(0xFFFFFFFFu, best, 2));
            if ((cx.lane & 3) == 0) wmax[q * 2 + (cx.w & 1)] = best;
        }
    __syncthreads();
    {
        unsigned long long m = umax64(wmax[cx.t * 2], wmax[cx.t * 2 + 1]);
        atomicMax(&g_best[u * BZd + cx.t], m);
    }
    __syncthreads();
}

__global__ void __launch_bounds__(256, 1)
scan_kernel(const float* __restrict__ keys, const float* __restrict__ R) {
    extern __shared__ float sm[];
    ScanCtx cx;
    cx.sm = sm;
    cx.sb4 = (uint32_t)__cvta_generic_to_shared(sm);
    cx.keys = keys;
    cx.R = R;
    cx.t = threadIdx.x;
    cx.lane = cx.t & 31;
    cx.w = cx.t >> 5;
    cx.L0 = blockIdx.x * 128;
    cx.m0g1 = (cx.w >> 1) * 32; cx.n0g1 = (cx.w & 1) * 64;
    cx.m0g2 = (cx.w >> 1) * 64; cx.n0g2 = (cx.w & 1) * 64;

    // unit 0: cols 0..255
    g1_panel(cx, 0, OF_KA);
    g1_panel(cx, 1, OF_KB);
    norms(cx, 256, 0);
    g2_resolve(cx, 0, 256, 0, 0);
    // unit 1: cols 256..511
    g1_panel(cx, 2, OF_KA);
    g1_panel(cx, 3, OF_KB);
    norms(cx, 256, 0);
    g2_resolve(cx, 1, 256, 256, 0);
    // units 2..4: 128 cols each
    g1_panel(cx, 4, OF_KA);
    norms(cx, 128, 0);
    g2_resolve(cx, 2, 128, 512, 0);
    g1_panel(cx, 5, OF_KA);
    norms(cx, 128, 0);
    g2_resolve(cx, 3, 128, 640, 0);
    g1_panel(cx, 6, OF_KA);
    norms(cx, 128, 0);
    g2_resolve(cx, 4, 128, 768, 0);
    // units 5,6: 64 cols each, share panel 7
    g1_panel(cx, 7, OF_KA);
    norms(cx, 64, 0);
    g2_resolve(cx, 5, 64, 896, 0);
    norms(cx, 64, 64);
    g2_resolve(cx, 6, 64, 960, 64);
}

// ================= K3: exact fp32 cosine of winners =================
__global__ void final_kernel(const float* __restrict__ keys, const float* __restrict__ R) {
    __shared__ float sv[H];
    __shared__ float sred[256];
    const int u = blockIdx.x >> 8;
    const int b = blockIdx.x & 255;
    const int t = threadIdx.x;
    unsigned long long pk = g_best[u * BZd + b];
    unsigned idx = 0xFFFFFFFFu - (unsigned)(pk & 0xFFFFFFFFull);
    const float* v = keys + (size_t)idx * H;
    for (int i = t; i < H; i += 256) sv[i] = v[i];
    __syncthreads();
    const int d = c_ud[u], off = c_uoff[u];
    const int rep = 256 / d;
    const int ip = t / d;
    const int c = t - ip * d;
    const int chunk = H / rep;
    const int i0 = ip * chunk;
    float part = 0.0f;
    {
        const float* Rc = R + off + c;
#pragma unroll 4
        for (int i = i0; i < i0 + chunk; ++i) part += sv[i] * Rc[(size_t)i * H];
    }
    sred[t] = part;
    __syncthreads();
    float dg = 0.0f, qc = 0.0f;
    if (t < d) {
        dg = sred[t];
        for (int r = 1; r < rep; ++r) dg += sred[t + r * d];
        qc = g_qrot[(size_t)b * H + off + t];
    }
    __syncthreads();
    float vals[3] = {qc * dg, dg * dg, qc * qc};
    float tot[3];
#pragma unroll
    for (int r = 0; r < 3; ++r) {
        sred[t] = vals[r];
        __syncthreads();
        for (int w = 128; w > 0; w >>= 1) {
            if (t < w) sred[t] += sred[t + w];
            __syncthreads();
        }
        tot[r] = sred[0];
        __syncthreads();
    }
    if (t == 0) {
        float cosv = tot[0] / (fmaxf(sqrtf(tot[2]), 1e-8f) * fmaxf(sqrtf(tot[1]), 1e-8f));
        g_cos[u * BZd + b] = cosv * (float)d;
    }
}

// ================= K4: deterministic reduction =================
__global__ void reduce_kernel(float* __restrict__ out) {
    __shared__ float sred[256];
    const int t = threadIdx.x;
    float s = 0.0f;
    for (int k = t; k < NU * BZd; k += 256) s += g_cos[k];
    sred[t] = s;
    __syncthreads();
    for (int w = 128; w > 0; w >>= 1) {
        if (t < w) sred[t] += sred[t + w];
        __syncthreads();
    }
    if (t == 0) out[0] = -sred[0] / (float)(BZd * H);
}

// ================= launch =================
extern "C" void kernel_launch(void* const* d_in, const int* in_sizes, int n_in,
                              void* d_out, int out_size) {
    const float* query = nullptr;
    const float* keys = nullptr;
    const float* R = nullptr;
    for (int i = 0; i < n_in; ++i) {
        if (in_sizes[i] == BZd * H) query = (const float*)d_in[i];
        else if (in_sizes[i] == NKEYS * H) keys = (const float*)d_in[i];
        else if (in_sizes[i] == H * H) R = (const float*)d_in[i];
    }
    if (!query) query = (const float*)d_in[0];
    if (!keys) keys = (const float*)d_in[1];
    if (!R) R = (const float*)d_in[2];
    float* out = (float*)d_out;

    cudaFuncSetAttribute(scan_kernel, cudaFuncAttributeMaxDynamicSharedMemorySize, SMEM_BYTES);

    qrot_kernel<<<32, 256>>>(query, R);
    qhat_kernel<<<256, 256>>>();
    scan_kernel<<<NKEYS / 128, 256, SMEM_BYTES>>>(keys, R);
    final_kernel<<<NU * BZd, 256>>>(keys, R);
    reduce_kernel<<<1, 256>>>(out);
}

// round 8
// speedup vs baseline: 3.2534x; 1.7270x over previous
#include <cuda_runtime.h>
#include <cuda_fp16.h>
#include <cstdint>

#define H 1024
#define BZd 256
#define NKEYS 131072
#define NU 7

__constant__ int c_ud[NU]   = {256, 256, 128, 128, 128, 64, 64};
__constant__ int c_uoff[NU] = {0, 256, 512, 640, 768, 896, 960};

__device__ __half g_keysh[(size_t)NKEYS * H];  // keys in fp16
__device__ __half g_Rth[H * H];                // R^T in fp16 ([n][k], k fast)
__device__ __half g_qh[BZd * H];               // qhat in fp16
__device__ float g_qrot[BZd * H];
__device__ unsigned long long g_best[NU * BZd];
__device__ float g_cos[NU * BZd];

// ---------------- smem layout (32-bit word offsets) ----------------
#define OF_KA 0                          // Krot panel A [128 keys][68 w] (fp16x2 packed)
#define OF_KB 8704                       // Krot panel B
#define OF_STA(b) (17408 + (b) * 2560)   // GEMM1 A stages x3: [128][20 w]
#define OF_STB(b) (25088 + (b) * 2560)   // GEMM1 B stages x3: [128][20 w]
#define OF_STQ(b) (17408 + (b) * 5120)   // GEMM2 Q stages x3: [256][20 w] (alias A/B)
#define OF_PART 32768                    // 256 floats
#define OF_RN 33024                      // 128 floats
#define OF_WMAX 33152                    // 512 u64 = 1024 words (8B aligned)
#define SMEM_WORDS 34176
#define SMEM_BYTES (SMEM_WORDS * 4)      // 136704

// ---------------- PTX helpers ----------------
#define CPA16(dst, src) \
    asm volatile("cp.async.cg.shared.global [%0], [%1], 16;" :: "r"(dst), "l"(src))
#define CPCOMMIT asm volatile("cp.async.commit_group;" ::: "memory")
#define CPWAIT1 asm volatile("cp.async.wait_group 1;" ::: "memory")
#define CPWAIT0 asm volatile("cp.async.wait_group 0;" ::: "memory")

__device__ __forceinline__ void mma16(float* d, const uint32_t* a, const uint32_t* b) {
    asm volatile(
        "mma.sync.aligned.m16n8k16.row.col.f32.f16.f16.f32 "
        "{%0,%1,%2,%3},{%4,%5,%6,%7},{%8,%9},{%0,%1,%2,%3};"
        : "+f"(d[0]), "+f"(d[1]), "+f"(d[2]), "+f"(d[3])
        : "r"(a[0]), "r"(a[1]), "r"(a[2]), "r"(a[3]), "r"(b[0]), "r"(b[1]));
}

__device__ __forceinline__ uint32_t h2bits(__half2 h) { return *(uint32_t*)&h; }

__device__ __forceinline__ unsigned long long umax64(unsigned long long a,
                                                     unsigned long long b) {
    return a > b ? a : b;
}

// ================= conversions =================
__global__ void convert_keys(const float* __restrict__ keys) {
    size_t i = (size_t)blockIdx.x * blockDim.x + threadIdx.x;  // float4 index
    float4 v = ((const float4*)keys)[i];
    __half2 h0 = __floats2half2_rn(v.x, v.y);
    __half2 h1 = __floats2half2_rn(v.z, v.w);
    uint2 w;
    w.x = h2bits(h0);
    w.y = h2bits(h1);
    ((uint2*)g_keysh)[i] = w;
}

__global__ void convert_Rt(const float* __restrict__ R) {
    __shared__ float tl[32][33];
    const int bx = blockIdx.x * 32, by = blockIdx.y * 32;
    const int tx = threadIdx.x, ty = threadIdx.y;
#pragma unroll
    for (int i = 0; i < 32; i += 8)
        tl[ty + i][tx] = R[(size_t)(by + ty + i) * H + bx + tx];
    __syncthreads();
#pragma unroll
    for (int i = 0; i < 32; i += 8)
        g_Rth[(size_t)(bx + ty + i) * H + by + tx] = __float2half_rn(tl[tx][ty + i]);
}

// ================= K1a: qrot = query @ R (exact fp32) =================
__global__ void qrot_kernel(const float* __restrict__ q, const float* __restrict__ R) {
    __shared__ float sq[2 * H];
    const int b0 = blockIdx.x * 2;
    const int t = threadIdx.x;
    for (int i = t; i < 2 * H; i += 256) sq[i] = q[(size_t)b0 * H + i];
    __syncthreads();
    float acc[2][4] = {};
    for (int i = 0; i < H; ++i) {
        const float* Rr = R + (size_t)i * H;
        float r0 = Rr[t], r1 = Rr[t + 256], r2 = Rr[t + 512], r3 = Rr[t + 768];
        float q0 = sq[i], q1 = sq[H + i];
        acc[0][0] += q0 * r0; acc[0][1] += q0 * r1;
        acc[0][2] += q0 * r2; acc[0][3] += q0 * r3;
        acc[1][0] += q1 * r0; acc[1][1] += q1 * r1;
        acc[1][2] += q1 * r2; acc[1][3] += q1 * r3;
    }
#pragma unroll
    for (int bb = 0; bb < 2; ++bb)
#pragma unroll
        for (int jj = 0; jj < 4; ++jj)
            g_qrot[(size_t)(b0 + bb) * H + t + jj * 256] = acc[bb][jj];
}

// ================= K1b: per-unit normalize -> fp16 qhat; init g_best =================
__global__ void qhat_kernel() {
    __shared__ float sx[H];
    __shared__ float sred[256];
    const int b = blockIdx.x, t = threadIdx.x;
    for (int i = t; i < H; i += 256) sx[i] = g_qrot[(size_t)b * H + i];
    if (b == 0) {
        for (int k = t; k < NU * BZd; k += 256) g_best[k] = 0x3FFFFFFF00000000ULL;
    }
    __syncthreads();
    for (int u = 0; u < NU; ++u) {
        const int d = c_ud[u], off = c_uoff[u];
        float s = 0.0f;
        for (int c = t; c < d; c += 256) { float v = sx[off + c]; s += v * v; }
        sred[t] = s;
        __syncthreads();
        for (int w = 128; w > 0; w >>= 1) {
            if (t < w) sred[t] += sred[t + w];
            __syncthreads();
        }
        float inv = 1.0f / fmaxf(sqrtf(sred[0]), 1e-8f);
        __syncthreads();
        for (int c = t; c < d; c += 256)
            g_qh[(size_t)b * H + off + c] = __float2half_rn(sx[off + c] * inv);
    }
}

// ================= K2: scan (mma.sync fp16) =================
// grid 1024 x 128 keys, block 256 (8 warps)
struct ScanCtx {
    float* sm;
    uint32_t* smw;
    uint32_t sb4;
    int t, lane, w, L0;
    int m0g1, n0g1, m0g2, n0g2;
};

__device__ __forceinline__ void stage_g1(const ScanCtx& cx, int p, int kk, int buf) {
    const int row = cx.t >> 1, hf = cx.t & 1;
    {
        const __half* src = g_keysh + (size_t)(cx.L0 + row) * H + kk * 32 + hf * 16;
        const uint32_t dst = cx.sb4 + (OF_STA(buf) + row * 20 + hf * 8) * 4;
        CPA16(dst, src);
        CPA16(dst + 16, src + 8);
    }
    {
        const __half* src = g_Rth + (size_t)(p * 128 + row) * H + kk * 32 + hf * 16;
        const uint32_t dst = cx.sb4 + (OF_STB(buf) + row * 20 + hf * 8) * 4;
        CPA16(dst, src);
        CPA16(dst + 16, src + 8);
    }
}

__device__ __forceinline__ void stage_q(const ScanCtx& cx, int qcol0, int buf) {
    const __half* src = g_qh + (size_t)cx.t * H + qcol0;
    const uint32_t dst = cx.sb4 + (OF_STQ(buf) + cx.t * 20) * 4;
    CPA16(dst, src);
    CPA16(dst + 16, src + 8);
    CPA16(dst + 32, src + 16);
    CPA16(dst + 48, src + 24);
}

// GEMM1: Krot panel [128 keys x 128 cols] = keys[128,1024] @ R[:, p*128:+128]
__device__ __forceinline__ void g1_panel(const ScanCtx& cx, int p, int kdst) {
    float acc1[2][8][4] = {};
    stage_g1(cx, p, 0, 0); CPCOMMIT;
    stage_g1(cx, p, 1, 1); CPCOMMIT;
    for (int kk = 0; kk < 32; ++kk) {
        if (kk < 31) { CPWAIT1; } else { CPWAIT0; }
        __syncthreads();
        if (kk + 2 < 32) { stage_g1(cx, p, kk + 2, (kk + 2) % 3); CPCOMMIT; }
        const uint32_t* wA = cx.smw + OF_STA(kk % 3);
        const uint32_t* wB = cx.smw + OF_STB(kk % 3);
#pragma unroll
        for (int k16 = 0; k16 < 2; ++k16) {
            uint32_t a[2][4];
#pragma unroll
            for (int i = 0; i < 2; ++i) {
                const int base = (cx.m0g1 + 16 * i + (cx.lane >> 2)) * 20 + k16 * 8 + (cx.lane & 3);
                a[i][0] = wA[base];
                a[i][1] = wA[base + 160];
                a[i][2] = wA[base + 4];
                a[i][3] = wA[base + 164];
            }
#pragma unroll
            for (int j = 0; j < 8; ++j) {
                const int wb = (cx.n0g1 + 8 * j + (cx.lane >> 2)) * 20 + k16 * 8 + (cx.lane & 3);
                uint32_t b[2] = {wB[wb], wB[wb + 4]};
                mma16(acc1[0][j], a[0], b);
                mma16(acc1[1][j], a[1], b);
            }
        }
    }
    // pack fp32 accum -> fp16x2 Krot panel
    uint32_t* Kd = cx.smw + kdst;
#pragma unroll
    for (int i = 0; i < 2; ++i)
#pragma unroll
        for (int j = 0; j < 8; ++j) {
            const int row = cx.m0g1 + 16 * i + (cx.lane >> 2);
            const int wj = (cx.n0g1 >> 1) + 4 * j + (cx.lane & 3);
            Kd[row * 68 + wj] = h2bits(__floats2half2_rn(acc1[i][j][0], acc1[i][j][1]));
            Kd[(row + 8) * 68 + wj] = h2bits(__floats2half2_rn(acc1[i][j][2], acc1[i][j][3]));
        }
    __syncthreads();
}

// per-key inverse norms over unit cols starting at word cbw, width W cols
__device__ __forceinline__ void norms(const ScanCtx& cx, int W, int cbw) {
    const int key = cx.t & 127, h = cx.t >> 7;
    const int cnt = W >> 2;
    const int wb = cbw + h * cnt;
    const uint32_t* base = (wb >= 64) ? (cx.smw + OF_KB + key * 68 + (wb - 64))
                                      : (cx.smw + OF_KA + key * 68 + wb);
    float s = 0.0f;
#pragma unroll 16
    for (int i = 0; i < cnt; ++i) {
        __half2 v = *(const __half2*)&base[i];
        float2 f = __half22float2(v);
        s += f.x * f.x + f.y * f.y;
    }
    cx.sm[OF_PART + cx.t] = s;
    __syncthreads();
    if (cx.t < 128) {
        float tot = cx.sm[OF_PART + cx.t] + cx.sm[OF_PART + cx.t + 128];
        cx.sm[OF_RN + cx.t] = 1.0f / fmaxf(sqrtf(tot), 1e-3f);
    }
    __syncthreads();
}

// GEMM2: sims[256 q x 128 keys] = qhat_u @ Krot_u^T, then argmax resolve
__device__ __forceinline__ void g2_resolve(const ScanCtx& cx, int u, int d, int qoff, int cbw) {
    float acc2[4][8][4] = {};
    const int nch = d >> 5;  // >= 2 always
    stage_q(cx, qoff, 0); CPCOMMIT;
    stage_q(cx, qoff + 32, 1); CPCOMMIT;
    for (int kc = 0; kc < nch; ++kc) {
        if (kc < nch - 1) { CPWAIT1; } else { CPWAIT0; }
        __syncthreads();
        if (kc + 2 < nch) { stage_q(cx, qoff + (kc + 2) * 32, (kc + 2) % 3); CPCOMMIT; }
        const uint32_t* wQ = cx.smw + OF_STQ(kc % 3);
#pragma unroll
        for (int k16 = 0; k16 < 2; ++k16) {
            const int kw = kc * 16 + k16 * 8;
            const uint32_t* wK;
            int wb0;
            if (d == 256 && kw >= 64) { wK = cx.smw + OF_KB; wb0 = kw - 64; }
            else { wK = cx.smw + OF_KA; wb0 = cbw + kw; }
            uint32_t a[4][4];
#pragma unroll
            for (int i = 0; i < 4; ++i) {
                const int base = (cx.m0g2 + 16 * i + (cx.lane >> 2)) * 20 + k16 * 8 + (cx.lane & 3);
                a[i][0] = wQ[base];
                a[i][1] = wQ[base + 160];
                a[i][2] = wQ[base + 4];
                a[i][3] = wQ[base + 164];
            }
#pragma unroll
            for (int j = 0; j < 8; ++j) {
                const int wb = (cx.n0g2 + 8 * j + (cx.lane >> 2)) * 68 + wb0 + (cx.lane & 3);
                uint32_t b[2] = {wK[wb], wK[wb + 4]};
#pragma unroll
                for (int i = 0; i < 4; ++i) mma16(acc2[i][j], a[i], b);
            }
        }
    }
    // resolve
    float rk[8][2];
#pragma unroll
    for (int j = 0; j < 8; ++j) {
        const int kl = cx.n0g2 + 8 * j + (cx.lane & 3) * 2;
        rk[j][0] = cx.sm[OF_RN + kl];
        rk[j][1] = cx.sm[OF_RN + kl + 1];
    }
    unsigned long long* wmax = (unsigned long long*)(cx.sm + OF_WMAX);
#pragma unroll
    for (int i = 0; i < 4; ++i)
#pragma unroll
        for (int hh = 0; hh < 2; ++hh) {
            const int q = cx.m0g2 + 16 * i + (cx.lane >> 2) + 8 * hh;
            unsigned long long best = 0ULL;
#pragma unroll
            for (int j = 0; j < 8; ++j)
#pragma unroll
                for (int e = 0; e < 2; ++e) {
                    float v = acc2[i][j][hh * 2 + e] * rk[j][e];
                    unsigned uv = __float_as_uint(v);
                    uv = (uv & 0x80000000u) ? ~uv : (uv | 0x80000000u);
                    const int kg = cx.L0 + cx.n0g2 + 8 * j + (cx.lane & 3) * 2 + e;
                    unsigned long long pk = ((unsigned long long)uv << 32) |
                                            (unsigned long long)(0xFFFFFFFFu - (unsigned)kg);
                    best = umax64(best, pk);
                }
            best = umax64(best, __shfl_xor_sync(0xFFFFFFFFu, best, 1));
            best = umax64(best, __shfl_xor_sync(0xFFFFFFFFu, best, 2));
            if ((cx.lane & 3) == 0) wmax[q * 2 + (cx.w & 1)] = best;
        }
    __syncthreads();
    {
        unsigned long long m = umax64(wmax[cx.t * 2], wmax[cx.t * 2 + 1]);
        atomicMax(&g_best[u * BZd + cx.t], m);
    }
    __syncthreads();
}

__global__ void __launch_bounds__(256, 1) scan_kernel() {
    extern __shared__ float sm[];
    ScanCtx cx;
    cx.sm = sm;
    cx.smw = (uint32_t*)sm;
    cx.sb4 = (uint32_t)__cvta_generic_to_shared(sm);
    cx.t = threadIdx.x;
    cx.lane = cx.t & 31;
    cx.w = cx.t >> 5;
    cx.L0 = blockIdx.x * 128;
    cx.m0g1 = (cx.w >> 1) * 32;
    cx.n0g1 = (cx.w & 1) * 64;
    cx.m0g2 = (cx.w >> 1) * 64;
    cx.n0g2 = (cx.w & 1) * 64;

    // unit 0: cols 0..255
    g1_panel(cx, 0, OF_KA);
    g1_panel(cx, 1, OF_KB);
    norms(cx, 256, 0);
    g2_resolve(cx, 0, 256, 0, 0);
    // unit 1: cols 256..511
    g1_panel(cx, 2, OF_KA);
    g1_panel(cx, 3, OF_KB);
    norms(cx, 256, 0);
    g2_resolve(cx, 1, 256, 256, 0);
    // units 2..4: 128 cols each
    g1_panel(cx, 4, OF_KA);
    norms(cx, 128, 0);
    g2_resolve(cx, 2, 128, 512, 0);
    g1_panel(cx, 5, OF_KA);
    norms(cx, 128, 0);
    g2_resolve(cx, 3, 128, 640, 0);
    g1_panel(cx, 6, OF_KA);
    norms(cx, 128, 0);
    g2_resolve(cx, 4, 128, 768, 0);
    // units 5,6: 64 cols each, share panel 7
    g1_panel(cx, 7, OF_KA);
    norms(cx, 64, 0);
    g2_resolve(cx, 5, 64, 896, 0);
    norms(cx, 64, 32);
    g2_resolve(cx, 6, 64, 960, 32);
}

// ================= K3: exact fp32 cosine of winners =================
__global__ void final_kernel(const float* __restrict__ keys, const float* __restrict__ R) {
    __shared__ float sv[H];
    __shared__ float sred[256];
    const int u = blockIdx.x >> 8;
    const int b = blockIdx.x & 255;
    const int t = threadIdx.x;
    unsigned long long pk = g_best[u * BZd + b];
    unsigned idx = 0xFFFFFFFFu - (unsigned)(pk & 0xFFFFFFFFull);
    const float* v = keys + (size_t)idx * H;
    for (int i = t; i < H; i += 256) sv[i] = v[i];
    __syncthreads();
    const int d = c_ud[u], off = c_uoff[u];
    const int rep = 256 / d;
    const int ip = t / d;
    const int c = t - ip * d;
    const int chunk = H / rep;
    const int i0 = ip * chunk;
    float part = 0.0f;
    {
        const float* Rc = R + off + c;
#pragma unroll 4
        for (int i = i0; i < i0 + chunk; ++i) part += sv[i] * Rc[(size_t)i * H];
    }
    sred[t] = part;
    __syncthreads();
    float dg = 0.0f, qc = 0.0f;
    if (t < d) {
        dg = sred[t];
        for (int r = 1; r < rep; ++r) dg += sred[t + r * d];
        qc = g_qrot[(size_t)b * H + off + t];
    }
    __syncthreads();
    float vals[3] = {qc * dg, dg * dg, qc * qc};
    float tot[3];
#pragma unroll
    for (int r = 0; r < 3; ++r) {
        sred[t] = vals[r];
        __syncthreads();
        for (int w = 128; w > 0; w >>= 1) {
            if (t < w) sred[t] += sred[t + w];
            __syncthreads();
        }
        tot[r] = sred[0];
        __syncthreads();
    }
    if (t == 0) {
        float cosv = tot[0] / (fmaxf(sqrtf(tot[2]), 1e-8f) * fmaxf(sqrtf(tot[1]), 1e-8f));
        g_cos[u * BZd + b] = cosv * (float)d;
    }
}

// ================= K4: deterministic reduction =================
__global__ void reduce_kernel(float* __restrict__ out) {
    __shared__ float sred[256];
    const int t = threadIdx.x;
    float s = 0.0f;
    for (int k = t; k < NU * BZd; k += 256) s += g_cos[k];
    sred[t] = s;
    __syncthreads();
    for (int w = 128; w > 0; w >>= 1) {
        if (t < w) sred[t] += sred[t + w];
        __syncthreads();
    }
    if (t == 0) out[0] = -sred[0] / (float)(BZd * H);
}

// ================= launch =================
extern "C" void kernel_launch(void* const* d_in, const int* in_sizes, int n_in,
                              void* d_out, int out_size) {
    const float* query = nullptr;
    const float* keys = nullptr;
    const float* R = nullptr;
    for (int i = 0; i < n_in; ++i) {
        if (in_sizes[i] == BZd * H) query = (const float*)d_in[i];
        else if (in_sizes[i] == NKEYS * H) keys = (const float*)d_in[i];
        else if (in_sizes[i] == H * H) R = (const float*)d_in[i];
    }
    if (!query) query = (const float*)d_in[0];
    if (!keys) keys = (const float*)d_in[1];
    if (!R) R = (const float*)d_in[2];
    float* out = (float*)d_out;

    cudaFuncSetAttribute(scan_kernel, cudaFuncAttributeMaxDynamicSharedMemorySize, SMEM_BYTES);

    convert_keys<<<(int)((size_t)NKEYS * H / 4 / 256), 256>>>(keys);
    convert_Rt<<<dim3(32, 32), dim3(32, 8)>>>(R);
    qrot_kernel<<<128, 256>>>(query, R);
    qhat_kernel<<<256, 256>>>();
    scan_kernel<<<1024, 256, SMEM_BYTES>>>();
    final_kernel<<<NU * BZd, 256>>>(keys, R);
    reduce_kernel<<<1, 256>>>(out);
}

// round 9
// speedup vs baseline: 3.3516x; 1.0302x over previous
#include <cuda_runtime.h>
#include <cuda_fp16.h>
#include <cstdint>

#define H 1024
#define BZd 256
#define NKEYS 131072
#define NU 7

__constant__ int c_ud[NU]   = {256, 256, 128, 128, 128, 64, 64};
__constant__ int c_uoff[NU] = {0, 256, 512, 640, 768, 896, 960};

__device__ __half g_keysh[(size_t)NKEYS * H];  // keys in fp16
__device__ __half g_Rth[H * H];                // R^T in fp16 ([n][k], k fast)
__device__ __half g_qh[BZd * H];               // qhat in fp16
__device__ float g_qrot[BZd * H];
__device__ unsigned long long g_best[NU * BZd];
__device__ float g_cos[NU * BZd];

// ---------------- smem layout (32-bit word offsets) ----------------
#define OF_KA 0                          // Krot panel A [128 keys][68 w] (fp16x2 packed)
#define OF_KB 8704                       // Krot panel B
#define OF_STA(b) (17408 + (b) * 2560)   // GEMM1 A stages x3: [128][20 w]
#define OF_STB(b) (25088 + (b) * 2560)   // GEMM1 B stages x3: [128][20 w]
#define OF_STQ(b) (17408 + (b) * 5120)   // GEMM2 Q stages x3: [256][20 w] (alias A/B)
#define OF_PART 32768                    // 256 floats
#define OF_RN 33024                      // 128 floats
#define OF_WMAX 33152                    // 512 u64 = 1024 words (8B aligned)
#define SMEM_WORDS 34176
#define SMEM_BYTES (SMEM_WORDS * 4)      // 136704

// ---------------- PTX helpers ----------------
#define CPA16(dst, src) \
    asm volatile("cp.async.cg.shared.global [%0], [%1], 16;" :: "r"(dst), "l"(src))
#define CPCOMMIT asm volatile("cp.async.commit_group;" ::: "memory")
#define CPWAIT1 asm volatile("cp.async.wait_group 1;" ::: "memory")
#define CPWAIT0 asm volatile("cp.async.wait_group 0;" ::: "memory")

__device__ __forceinline__ void mma16(float* d, const uint32_t* a, const uint32_t* b) {
    asm volatile(
        "mma.sync.aligned.m16n8k16.row.col.f32.f16.f16.f32 "
        "{%0,%1,%2,%3},{%4,%5,%6,%7},{%8,%9},{%0,%1,%2,%3};"
        : "+f"(d[0]), "+f"(d[1]), "+f"(d[2]), "+f"(d[3])
        : "r"(a[0]), "r"(a[1]), "r"(a[2]), "r"(a[3]), "r"(b[0]), "r"(b[1]));
}

__device__ __forceinline__ void ldsm4(uint32_t* r, uint32_t addr) {
    asm volatile("ldmatrix.sync.aligned.m8n8.x4.shared.b16 {%0,%1,%2,%3}, [%4];"
                 : "=r"(r[0]), "=r"(r[1]), "=r"(r[2]), "=r"(r[3]) : "r"(addr));
}

__device__ __forceinline__ uint32_t h2bits(__half2 h) { return *(uint32_t*)&h; }

__device__ __forceinline__ unsigned long long umax64(unsigned long long a,
                                                     unsigned long long b) {
    return a > b ? a : b;
}

// ================= conversions =================
__global__ void convert_keys(const float* __restrict__ keys) {
    size_t i = (size_t)blockIdx.x * blockDim.x + threadIdx.x;  // float4 index
    float4 v = ((const float4*)keys)[i];
    __half2 h0 = __floats2half2_rn(v.x, v.y);
    __half2 h1 = __floats2half2_rn(v.z, v.w);
    uint2 w;
    w.x = h2bits(h0);
    w.y = h2bits(h1);
    ((uint2*)g_keysh)[i] = w;
}

__global__ void convert_Rt(const float* __restrict__ R) {
    __shared__ float tl[32][33];
    const int bx = blockIdx.x * 32, by = blockIdx.y * 32;
    const int tx = threadIdx.x, ty = threadIdx.y;
#pragma unroll
    for (int i = 0; i < 32; i += 8)
        tl[ty + i][tx] = R[(size_t)(by + ty + i) * H + bx + tx];
    __syncthreads();
#pragma unroll
    for (int i = 0; i < 32; i += 8)
        g_Rth[(size_t)(bx + ty + i) * H + by + tx] = __float2half_rn(tl[tx][ty + i]);
}

// ================= K1a: qrot = query @ R (exact fp32) =================
__global__ void qrot_kernel(const float* __restrict__ q, const float* __restrict__ R) {
    __shared__ float sq[2 * H];
    const int b0 = blockIdx.x * 2;
    const int t = threadIdx.x;
    for (int i = t; i < 2 * H; i += 256) sq[i] = q[(size_t)b0 * H + i];
    __syncthreads();
    float acc[2][4] = {};
    for (int i = 0; i < H; ++i) {
        const float* Rr = R + (size_t)i * H;
        float r0 = Rr[t], r1 = Rr[t + 256], r2 = Rr[t + 512], r3 = Rr[t + 768];
        float q0 = sq[i], q1 = sq[H + i];
        acc[0][0] += q0 * r0; acc[0][1] += q0 * r1;
        acc[0][2] += q0 * r2; acc[0][3] += q0 * r3;
        acc[1][0] += q1 * r0; acc[1][1] += q1 * r1;
        acc[1][2] += q1 * r2; acc[1][3] += q1 * r3;
    }
#pragma unroll
    for (int bb = 0; bb < 2; ++bb)
#pragma unroll
        for (int jj = 0; jj < 4; ++jj)
            g_qrot[(size_t)(b0 + bb) * H + t + jj * 256] = acc[bb][jj];
}

// ================= K1b: per-unit normalize -> fp16 qhat; init g_best =================
__global__ void qhat_kernel() {
    __shared__ float sx[H];
    __shared__ float sred[256];
    const int b = blockIdx.x, t = threadIdx.x;
    for (int i = t; i < H; i += 256) sx[i] = g_qrot[(size_t)b * H + i];
    if (b == 0) {
        for (int k = t; k < NU * BZd; k += 256) g_best[k] = 0x3FFFFFFF00000000ULL;
    }
    __syncthreads();
    for (int u = 0; u < NU; ++u) {
        const int d = c_ud[u], off = c_uoff[u];
        float s = 0.0f;
        for (int c = t; c < d; c += 256) { float v = sx[off + c]; s += v * v; }
        sred[t] = s;
        __syncthreads();
        for (int w = 128; w > 0; w >>= 1) {
            if (t < w) sred[t] += sred[t + w];
            __syncthreads();
        }
        float inv = 1.0f / fmaxf(sqrtf(sred[0]), 1e-8f);
        __syncthreads();
        for (int c = t; c < d; c += 256)
            g_qh[(size_t)b * H + off + c] = __float2half_rn(sx[off + c] * inv);
    }
}

// ================= K2: scan (mma.sync fp16 + ldmatrix) =================
// grid 1024 x 128 keys, block 256 (8 warps)
struct ScanCtx {
    float* sm;
    uint32_t* smw;
    uint32_t sb4;
    int t, lane, w, L0;
    int m0g1, n0g1, m0g2, n0g2;
    uint32_t offA1, offB1, offA2, offB2;  // per-lane ldmatrix byte offsets
};

__device__ __forceinline__ void stage_g1(const ScanCtx& cx, int p, int kk, int buf) {
    const int row = cx.t >> 1, hf = cx.t & 1;
    {
        const __half* src = g_keysh + (size_t)(cx.L0 + row) * H + kk * 32 + hf * 16;
        const uint32_t dst = cx.sb4 + (OF_STA(buf) + row * 20 + hf * 8) * 4;
        CPA16(dst, src);
        CPA16(dst + 16, src + 8);
    }
    {
        const __half* src = g_Rth + (size_t)(p * 128 + row) * H + kk * 32 + hf * 16;
        const uint32_t dst = cx.sb4 + (OF_STB(buf) + row * 20 + hf * 8) * 4;
        CPA16(dst, src);
        CPA16(dst + 16, src + 8);
    }
}

__device__ __forceinline__ void stage_q(const ScanCtx& cx, int qcol0, int buf) {
    const __half* src = g_qh + (size_t)cx.t * H + qcol0;
    const uint32_t dst = cx.sb4 + (OF_STQ(buf) + cx.t * 20) * 4;
    CPA16(dst, src);
    CPA16(dst + 16, src + 8);
    CPA16(dst + 32, src + 16);
    CPA16(dst + 48, src + 24);
}

// GEMM1: Krot panel [128 keys x 128 cols] = keys[128,1024] @ R[:, p*128:+128]
__device__ __forceinline__ void g1_panel(const ScanCtx& cx, int p, int kdst) {
    float acc1[2][8][4] = {};
    stage_g1(cx, p, 0, 0); CPCOMMIT;
    stage_g1(cx, p, 1, 1); CPCOMMIT;
    for (int kk = 0; kk < 32; ++kk) {
        if (kk < 31) { CPWAIT1; } else { CPWAIT0; }
        __syncthreads();
        if (kk + 2 < 32) { stage_g1(cx, p, kk + 2, (kk + 2) % 3); CPCOMMIT; }
        const uint32_t baseA = cx.sb4 + OF_STA(kk % 3) * 4 + cx.offA1;
        const uint32_t baseB = cx.sb4 + OF_STB(kk % 3) * 4 + cx.offB1;
#pragma unroll
        for (int k16 = 0; k16 < 2; ++k16) {
            uint32_t a[2][4];
            ldsm4(a[0], baseA + k16 * 32);
            ldsm4(a[1], baseA + 1280 + k16 * 32);  // +16 rows * 80B
            uint32_t bb[4][4];
#pragma unroll
            for (int jj = 0; jj < 4; ++jj)
                ldsm4(bb[jj], baseB + jj * 1280 + k16 * 32);
#pragma unroll
            for (int jj = 0; jj < 4; ++jj) {
                mma16(acc1[0][2 * jj],     a[0], &bb[jj][0]);
                mma16(acc1[0][2 * jj + 1], a[0], &bb[jj][2]);
                mma16(acc1[1][2 * jj],     a[1], &bb[jj][0]);
                mma16(acc1[1][2 * jj + 1], a[1], &bb[jj][2]);
            }
        }
    }
    // pack fp32 accum -> fp16x2 Krot panel
    uint32_t* Kd = cx.smw + kdst;
#pragma unroll
    for (int i = 0; i < 2; ++i)
#pragma unroll
        for (int j = 0; j < 8; ++j) {
            const int row = cx.m0g1 + 16 * i + (cx.lane >> 2);
            const int wj = (cx.n0g1 >> 1) + 4 * j + (cx.lane & 3);
            Kd[row * 68 + wj] = h2bits(__floats2half2_rn(acc1[i][j][0], acc1[i][j][1]));
            Kd[(row + 8) * 68 + wj] = h2bits(__floats2half2_rn(acc1[i][j][2], acc1[i][j][3]));
        }
    __syncthreads();
}

// per-key inverse norms over unit cols starting at word cbw, width W cols
__device__ __forceinline__ void norms(const ScanCtx& cx, int W, int cbw) {
    const int key = cx.t & 127, h = cx.t >> 7;
    const int cnt = W >> 2;
    const int wb = cbw + h * cnt;
    const uint32_t* base = (wb >= 64) ? (cx.smw + OF_KB + key * 68 + (wb - 64))
                                      : (cx.smw + OF_KA + key * 68 + wb);
    float s = 0.0f;
#pragma unroll 16
    for (int i = 0; i < cnt; ++i) {
        __half2 v = *(const __half2*)&base[i];
        float2 f = __half22float2(v);
        s += f.x * f.x + f.y * f.y;
    }
    cx.sm[OF_PART + cx.t] = s;
    __syncthreads();
    if (cx.t < 128) {
        float tot = cx.sm[OF_PART + cx.t] + cx.sm[OF_PART + cx.t + 128];
        cx.sm[OF_RN + cx.t] = 1.0f / fmaxf(sqrtf(tot), 1e-3f);
    }
    __syncthreads();
}

// GEMM2: sims[256 q x 128 keys] = qhat_u @ Krot_u^T, then argmax resolve
__device__ __forceinline__ void g2_resolve(const ScanCtx& cx, int u, int d, int qoff, int cbw) {
    float acc2[4][8][4] = {};
    const int nch = d >> 5;  // >= 2 always
    stage_q(cx, qoff, 0); CPCOMMIT;
    stage_q(cx, qoff + 32, 1); CPCOMMIT;
    for (int kc = 0; kc < nch; ++kc) {
        if (kc < nch - 1) { CPWAIT1; } else { CPWAIT0; }
        __syncthreads();
        if (kc + 2 < nch) { stage_q(cx, qoff + (kc + 2) * 32, (kc + 2) % 3); CPCOMMIT; }
        const uint32_t baseQ = cx.sb4 + OF_STQ(kc % 3) * 4 + cx.offA2;
#pragma unroll
        for (int k16 = 0; k16 < 2; ++k16) {
            const int kw = kc * 16 + k16 * 8;
            uint32_t baseK;
            if (d == 256 && kw >= 64)
                baseK = cx.sb4 + OF_KB * 4 + (kw - 64) * 4 + cx.offB2;
            else
                baseK = cx.sb4 + OF_KA * 4 + (cbw + kw) * 4 + cx.offB2;
            uint32_t a[4][4];
#pragma unroll
            for (int i = 0; i < 4; ++i)
                ldsm4(a[i], baseQ + i * 1280 + k16 * 32);
            uint32_t bb[4][4];
#pragma unroll
            for (int jj = 0; jj < 4; ++jj)
                ldsm4(bb[jj], baseK + jj * 4352);  // 16 keys * 272B
#pragma unroll
            for (int jj = 0; jj < 4; ++jj)
#pragma unroll
                for (int i = 0; i < 4; ++i) {
                    mma16(acc2[i][2 * jj],     a[i], &bb[jj][0]);
                    mma16(acc2[i][2 * jj + 1], a[i], &bb[jj][2]);
                }
        }
    }
    // resolve
    float rk[8][2];
#pragma unroll
    for (int j = 0; j < 8; ++j) {
        const int kl = cx.n0g2 + 8 * j + (cx.lane & 3) * 2;
        rk[j][0] = cx.sm[OF_RN + kl];
        rk[j][1] = cx.sm[OF_RN + kl + 1];
    }
    unsigned long long* wmax = (unsigned long long*)(cx.sm + OF_WMAX);
#pragma unroll
    for (int i = 0; i < 4; ++i)
#pragma unroll
        for (int hh = 0; hh < 2; ++hh) {
            const int q = cx.m0g2 + 16 * i + (cx.lane >> 2) + 8 * hh;
            unsigned long long best = 0ULL;
#pragma unroll
            for (int j = 0; j < 8; ++j)
#pragma unroll
                for (int e = 0; e < 2; ++e) {
                    float v = acc2[i][j][hh * 2 + e] * rk[j][e];
                    unsigned uv = __float_as_uint(v);
                    uv = (uv & 0x80000000u) ? ~uv : (uv | 0x80000000u);
                    const int kg = cx.L0 + cx.n0g2 + 8 * j + (cx.lane & 3) * 2 + e;
                    unsigned long long pk = ((unsigned long long)uv << 32) |
                                            (unsigned long long)(0xFFFFFFFFu - (unsigned)kg);
                    best = umax64(best, pk);
                }
            best = umax64(best, __shfl_xor_sync(0xFFFFFFFFu, best, 1));
            best = umax64(best, __shfl_xor_sync(0xFFFFFFFFu, best, 2));
            if ((cx.lane & 3) == 0) wmax[q * 2 + (cx.w & 1)] = best;
        }
    __syncthreads();
    {
        unsigned long long m = umax64(wmax[cx.t * 2], wmax[cx.t * 2 + 1]);
        atomicMax(&g_best[u * BZd + cx.t], m);
    }
    __syncthreads();
}

__global__ void __launch_bounds__(256, 1) scan_kernel() {
    extern __shared__ float sm[];
    ScanCtx cx;
    cx.sm = sm;
    cx.smw = (uint32_t*)sm;
    cx.sb4 = (uint32_t)__cvta_generic_to_shared(sm);
    cx.t = threadIdx.x;
    cx.lane = cx.t & 31;
    cx.w = cx.t >> 5;
    cx.L0 = blockIdx.x * 128;
    cx.m0g1 = (cx.w >> 1) * 32;
    cx.n0g1 = (cx.w & 1) * 64;
    cx.m0g2 = (cx.w >> 1) * 64;
    cx.n0g2 = (cx.w & 1) * 64;
    {
        const int l = cx.lane;
        // A-style frag (rows r, r+8 / cols 0, +16B): row+8 on bit3, byte+16 on bit4
        cx.offA1 = (uint32_t)((cx.m0g1 + (l & 7) + 8 * ((l >> 3) & 1)) * 80 + 16 * (l >> 4));
        cx.offA2 = (uint32_t)((cx.m0g2 + (l & 7) + 8 * ((l >> 3) & 1)) * 80 + 16 * (l >> 4));
        // B-style frag (rows n, n+8 on bit4 / k-bytes 0, +16 on bit3)
        cx.offB1 = (uint32_t)((cx.n0g1 + (l & 7) + 8 * (l >> 4)) * 80 + 16 * ((l >> 3) & 1));
        cx.offB2 = (uint32_t)((cx.n0g2 + (l & 7) + 8 * (l >> 4)) * 272 + 16 * ((l >> 3) & 1));
    }

    // unit 0: cols 0..255
    g1_panel(cx, 0, OF_KA);
    g1_panel(cx, 1, OF_KB);
    norms(cx, 256, 0);
    g2_resolve(cx, 0, 256, 0, 0);
    // unit 1: cols 256..511
    g1_panel(cx, 2, OF_KA);
    g1_panel(cx, 3, OF_KB);
    norms(cx, 256, 0);
    g2_resolve(cx, 1, 256, 256, 0);
    // units 2..4: 128 cols each
    g1_panel(cx, 4, OF_KA);
    norms(cx, 128, 0);
    g2_resolve(cx, 2, 128, 512, 0);
    g1_panel(cx, 5, OF_KA);
    norms(cx, 128, 0);
    g2_resolve(cx, 3, 128, 640, 0);
    g1_panel(cx, 6, OF_KA);
    norms(cx, 128, 0);
    g2_resolve(cx, 4, 128, 768, 0);
    // units 5,6: 64 cols each, share panel 7
    g1_panel(cx, 7, OF_KA);
    norms(cx, 64, 0);
    g2_resolve(cx, 5, 64, 896, 0);
    norms(cx, 64, 32);
    g2_resolve(cx, 6, 64, 960, 32);
}

// ================= K3: exact fp32 cosine of winners =================
__global__ void final_kernel(const float* __restrict__ keys, const float* __restrict__ R) {
    __shared__ float sv[H];
    __shared__ float sred[256];
    const int u = blockIdx.x >> 8;
    const int b = blockIdx.x & 255;
    const int t = threadIdx.x;
    unsigned long long pk = g_best[u * BZd + b];
    unsigned idx = 0xFFFFFFFFu - (unsigned)(pk & 0xFFFFFFFFull);
    const float* v = keys + (size_t)idx * H;
    for (int i = t; i < H; i += 256) sv[i] = v[i];
    __syncthreads();
    const int d = c_ud[u], off = c_uoff[u];
    const int rep = 256 / d;
    const int ip = t / d;
    const int c = t - ip * d;
    const int chunk = H / rep;
    const int i0 = ip * chunk;
    float part = 0.0f;
    {
        const float* Rc = R + off + c;
#pragma unroll 4
        for (int i = i0; i < i0 + chunk; ++i) part += sv[i] * Rc[(size_t)i * H];
    }
    sred[t] = part;
    __syncthreads();
    float dg = 0.0f, qc = 0.0f;
    if (t < d) {
        dg = sred[t];
        for (int r = 1; r < rep; ++r) dg += sred[t + r * d];
        qc = g_qrot[(size_t)b * H + off + t];
    }
    __syncthreads();
    float vals[3] = {qc * dg, dg * dg, qc * qc};
    float tot[3];
#pragma unroll
    for (int r = 0; r < 3; ++r) {
        sred[t] = vals[r];
        __syncthreads();
        for (int w = 128; w > 0; w >>= 1) {
            if (t < w) sred[t] += sred[t + w];
            __syncthreads();
        }
        tot[r] = sred[0];
        __syncthreads();
    }
    if (t == 0) {
        float cosv = tot[0] / (fmaxf(sqrtf(tot[2]), 1e-8f) * fmaxf(sqrtf(tot[1]), 1e-8f));
        g_cos[u * BZd + b] = cosv * (float)d;
    }
}

// ================= K4: deterministic reduction =================
__global__ void reduce_kernel(float* __restrict__ out) {
    __shared__ float sred[256];
    const int t = threadIdx.x;
    float s = 0.0f;
    for (int k = t; k < NU * BZd; k += 256) s += g_cos[k];
    sred[t] = s;
    __syncthreads();
    for (int w = 128; w > 0; w >>= 1) {
        if (t < w) sred[t] += sred[t + w];
        __syncthreads();
    }
    if (t == 0) out[0] = -sred[0] / (float)(BZd * H);
}

// ================= launch =================
extern "C" void kernel_launch(void* const* d_in, const int* in_sizes, int n_in,
                              void* d_out, int out_size) {
    const float* query = nullptr;
    const float* keys = nullptr;
    const float* R = nullptr;
    for (int i = 0; i < n_in; ++i) {
        if (in_sizes[i] == BZd * H) query = (const float*)d_in[i];
        else if (in_sizes[i] == NKEYS * H) keys = (const float*)d_in[i];
        else if (in_sizes[i] == H * H) R = (const float*)d_in[i];
    }
    if (!query) query = (const float*)d_in[0];
    if (!keys) keys = (const float*)d_in[1];
    if (!R) R = (const float*)d_in[2];
    float* out = (float*)d_out;

    cudaFuncSetAttribute(scan_kernel, cudaFuncAttributeMaxDynamicSharedMemorySize, SMEM_BYTES);

    convert_keys<<<(int)((size_t)NKEYS * H / 4 / 256), 256>>>(keys);
    convert_Rt<<<dim3(32, 32), dim3(32, 8)>>>(R);
    qrot_kernel<<<128, 256>>>(query, R);
    qhat_kernel<<<256, 256>>>();
    scan_kernel<<<1024, 256, SMEM_BYTES>>>();
    final_kernel<<<NU * BZd, 256>>>(keys, R);
    reduce_kernel<<<1, 256>>>(out);
}

// round 10
// speedup vs baseline: 5.4814x; 1.6355x over previous
#include <cuda_runtime.h>
#include <cuda_fp16.h>
#include <cstdint>

#define H 1024
#define BZd 256
#define NKEYS 131072
#define NU 7

#define SK 21.0f
#define SR 750.0f
#define DQS (1.0f / (21.0f * 750.0f))

__constant__ int c_ud[NU]   = {256, 256, 128, 128, 128, 64, 64};
__constant__ int c_uoff[NU] = {0, 256, 512, 640, 768, 896, 960};

__device__ int8_t g_keys8[(size_t)NKEYS * H];  // keys quantized (x21)
__device__ int8_t g_Rt8[H * H];                // R^T quantized (x750), [n][k] k fast
__device__ __half g_qh[BZd * H];               // qhat in fp16
__device__ float g_qrot[BZd * H];
__device__ unsigned long long g_best[NU * BZd];
__device__ float g_cos[NU * BZd];

// ---------------- smem layout (32-bit word offsets) ----------------
#define OF_KA 0                          // Krot panel A [128 keys][68 w] (fp16x2 packed)
#define OF_KB 8704                       // Krot panel B
#define OF_STA(b) (17408 + (b) * 2560)   // GEMM1 A stages x3: [128 rows][80 B]
#define OF_STB(b) (25088 + (b) * 2560)   // GEMM1 B stages x3: [128 rows][80 B]
#define OF_STQ(b) (17408 + (b) * 5120)   // GEMM2 Q stages x3: [256][20 w] (alias A/B)
#define OF_PART 32768                    // 256 floats
#define OF_RN 33024                      // 128 floats
#define OF_WMAX 33152                    // 512 u64 = 1024 words (8B aligned)
#define SMEM_WORDS 34176
#define SMEM_BYTES (SMEM_WORDS * 4)      // 136704

// ---------------- PTX helpers ----------------
#define CPA16(dst, src) \
    asm volatile("cp.async.cg.shared.global [%0], [%1], 16;" :: "r"(dst), "l"(src))
#define CPCOMMIT asm volatile("cp.async.commit_group;" ::: "memory")
#define CPWAIT1 asm volatile("cp.async.wait_group 1;" ::: "memory")
#define CPWAIT0 asm volatile("cp.async.wait_group 0;" ::: "memory")

__device__ __forceinline__ void mma16(float* d, const uint32_t* a, const uint32_t* b) {
    asm volatile(
        "mma.sync.aligned.m16n8k16.row.col.f32.f16.f16.f32 "
        "{%0,%1,%2,%3},{%4,%5,%6,%7},{%8,%9},{%0,%1,%2,%3};"
        : "+f"(d[0]), "+f"(d[1]), "+f"(d[2]), "+f"(d[3])
        : "r"(a[0]), "r"(a[1]), "r"(a[2]), "r"(a[3]), "r"(b[0]), "r"(b[1]));
}

__device__ __forceinline__ void mma_s8(int* d, const uint32_t* a, const uint32_t* b) {
    asm volatile(
        "mma.sync.aligned.m16n8k32.row.col.s32.s8.s8.s32 "
        "{%0,%1,%2,%3},{%4,%5,%6,%7},{%8,%9},{%0,%1,%2,%3};"
        : "+r"(d[0]), "+r"(d[1]), "+r"(d[2]), "+r"(d[3])
        : "r"(a[0]), "r"(a[1]), "r"(a[2]), "r"(a[3]), "r"(b[0]), "r"(b[1]));
}

__device__ __forceinline__ void ldsm4(uint32_t* r, uint32_t addr) {
    asm volatile("ldmatrix.sync.aligned.m8n8.x4.shared.b16 {%0,%1,%2,%3}, [%4];"
                 : "=r"(r[0]), "=r"(r[1]), "=r"(r[2]), "=r"(r[3]) : "r"(addr));
}

__device__ __forceinline__ uint32_t h2bits(__half2 h) { return *(uint32_t*)&h; }

__device__ __forceinline__ unsigned long long umax64(unsigned long long a,
                                                     unsigned long long b) {
    return a > b ? a : b;
}

__device__ __forceinline__ int8_t q8(float v, float s) {
    int x = __float2int_rn(v * s);
    x = x > 127 ? 127 : (x < -127 ? -127 : x);
    return (int8_t)x;
}

// ================= quantization =================
__global__ void quant_keys(const float* __restrict__ keys) {
    size_t i = (size_t)blockIdx.x * blockDim.x + threadIdx.x;  // float4 index
    float4 v = ((const float4*)keys)[i];
    char4 c;
    c.x = q8(v.x, SK); c.y = q8(v.y, SK); c.z = q8(v.z, SK); c.w = q8(v.w, SK);
    ((char4*)g_keys8)[i] = c;
}

__global__ void quant_Rt(const float* __restrict__ R) {
    __shared__ float tl[32][33];
    const int bx = blockIdx.x * 32, by = blockIdx.y * 32;
    const int tx = threadIdx.x, ty = threadIdx.y;
#pragma unroll
    for (int i = 0; i < 32; i += 8)
        tl[ty + i][tx] = R[(size_t)(by + ty + i) * H + bx + tx];
    __syncthreads();
#pragma unroll
    for (int i = 0; i < 32; i += 8)
        g_Rt8[(size_t)(bx + ty + i) * H + by + tx] = q8(tl[tx][ty + i], SR);
}

// ================= K1a: qrot = query @ R (exact fp32) =================
__global__ void qrot_kernel(const float* __restrict__ q, const float* __restrict__ R) {
    __shared__ float sq[2 * H];
    const int b0 = blockIdx.x * 2;
    const int t = threadIdx.x;
    for (int i = t; i < 2 * H; i += 256) sq[i] = q[(size_t)b0 * H + i];
    __syncthreads();
    float acc[2][4] = {};
    for (int i = 0; i < H; ++i) {
        const float* Rr = R + (size_t)i * H;
        float r0 = Rr[t], r1 = Rr[t + 256], r2 = Rr[t + 512], r3 = Rr[t + 768];
        float q0 = sq[i], q1 = sq[H + i];
        acc[0][0] += q0 * r0; acc[0][1] += q0 * r1;
        acc[0][2] += q0 * r2; acc[0][3] += q0 * r3;
        acc[1][0] += q1 * r0; acc[1][1] += q1 * r1;
        acc[1][2] += q1 * r2; acc[1][3] += q1 * r3;
    }
#pragma unroll
    for (int bb = 0; bb < 2; ++bb)
#pragma unroll
        for (int jj = 0; jj < 4; ++jj)
            g_qrot[(size_t)(b0 + bb) * H + t + jj * 256] = acc[bb][jj];
}

// ================= K1b: per-unit normalize -> fp16 qhat; init g_best =================
__global__ void qhat_kernel() {
    __shared__ float sx[H];
    __shared__ float sred[256];
    const int b = blockIdx.x, t = threadIdx.x;
    for (int i = t; i < H; i += 256) sx[i] = g_qrot[(size_t)b * H + i];
    if (b == 0) {
        for (int k = t; k < NU * BZd; k += 256) g_best[k] = 0x3FFFFFFF00000000ULL;
    }
    __syncthreads();
    for (int u = 0; u < NU; ++u) {
        const int d = c_ud[u], off = c_uoff[u];
        float s = 0.0f;
        for (int c = t; c < d; c += 256) { float v = sx[off + c]; s += v * v; }
        sred[t] = s;
        __syncthreads();
        for (int w = 128; w > 0; w >>= 1) {
            if (t < w) sred[t] += sred[t + w];
            __syncthreads();
        }
        float inv = 1.0f / fmaxf(sqrtf(sred[0]), 1e-8f);
        __syncthreads();
        for (int c = t; c < d; c += 256)
            g_qh[(size_t)b * H + off + c] = __float2half_rn(sx[off + c] * inv);
    }
}

// ================= K2: scan (int8 GEMM1 + fp16 GEMM2, ldmatrix) =================
// grid 1024 x 128 keys, block 256 (8 warps)
struct ScanCtx {
    float* sm;
    uint32_t* smw;
    uint32_t sb4;
    int t, lane, w, L0;
    int m0g1, n0g1, m0g2, n0g2;
    uint32_t offA1, offB1, offA2, offB2;  // per-lane ldmatrix byte offsets
};

// stage int8: 128 rows x 64 bytes (k-chunk of 64 elements), row pitch 80 B
__device__ __forceinline__ void stage_g1(const ScanCtx& cx, int p, int kk, int buf) {
    const int row = cx.t >> 1, hf = cx.t & 1;
    {
        const int8_t* src = g_keys8 + (size_t)(cx.L0 + row) * H + kk * 64 + hf * 32;
        const uint32_t dst = cx.sb4 + OF_STA(buf) * 4 + row * 80 + hf * 32;
        CPA16(dst, src);
        CPA16(dst + 16, src + 16);
    }
    {
        const int8_t* src = g_Rt8 + (size_t)(p * 128 + row) * H + kk * 64 + hf * 32;
        const uint32_t dst = cx.sb4 + OF_STB(buf) * 4 + row * 80 + hf * 32;
        CPA16(dst, src);
        CPA16(dst + 16, src + 16);
    }
}

__device__ __forceinline__ void stage_q(const ScanCtx& cx, int qcol0, int buf) {
    const __half* src = g_qh + (size_t)cx.t * H + qcol0;
    const uint32_t dst = cx.sb4 + (OF_STQ(buf) + cx.t * 20) * 4;
    CPA16(dst, src);
    CPA16(dst + 16, src + 8);
    CPA16(dst + 32, src + 16);
    CPA16(dst + 48, src + 24);
}

// GEMM1 (int8): Krot panel [128 keys x 128 cols] = keys[128,1024] @ R[:, p*128:+128]
__device__ __forceinline__ void g1_panel(const ScanCtx& cx, int p, int kdst) {
    int acc1[2][8][4] = {};
    stage_g1(cx, p, 0, 0); CPCOMMIT;
    stage_g1(cx, p, 1, 1); CPCOMMIT;
    for (int kk = 0; kk < 16; ++kk) {
        if (kk < 15) { CPWAIT1; } else { CPWAIT0; }
        __syncthreads();
        if (kk + 2 < 16) { stage_g1(cx, p, kk + 2, (kk + 2) % 3); CPCOMMIT; }
        const uint32_t baseA = cx.sb4 + OF_STA(kk % 3) * 4 + cx.offA1;
        const uint32_t baseB = cx.sb4 + OF_STB(kk % 3) * 4 + cx.offB1;
#pragma unroll
        for (int k32 = 0; k32 < 2; ++k32) {
            uint32_t a[2][4];
            ldsm4(a[0], baseA + k32 * 32);
            ldsm4(a[1], baseA + 1280 + k32 * 32);  // +16 rows * 80B
            uint32_t bb[4][4];
#pragma unroll
            for (int jj = 0; jj < 4; ++jj)
                ldsm4(bb[jj], baseB + jj * 1280 + k32 * 32);
#pragma unroll
            for (int jj = 0; jj < 4; ++jj) {
                mma_s8(acc1[0][2 * jj],     a[0], &bb[jj][0]);
                mma_s8(acc1[0][2 * jj + 1], a[0], &bb[jj][2]);
                mma_s8(acc1[1][2 * jj],     a[1], &bb[jj][0]);
                mma_s8(acc1[1][2 * jj + 1], a[1], &bb[jj][2]);
            }
        }
    }
    // dequantize s32 accum -> fp16x2 Krot panel
    uint32_t* Kd = cx.smw + kdst;
#pragma unroll
    for (int i = 0; i < 2; ++i)
#pragma unroll
        for (int j = 0; j < 8; ++j) {
            const int row = cx.m0g1 + 16 * i + (cx.lane >> 2);
            const int wj = (cx.n0g1 >> 1) + 4 * j + (cx.lane & 3);
            Kd[row * 68 + wj] = h2bits(__floats2half2_rn(
                (float)acc1[i][j][0] * DQS, (float)acc1[i][j][1] * DQS));
            Kd[(row + 8) * 68 + wj] = h2bits(__floats2half2_rn(
                (float)acc1[i][j][2] * DQS, (float)acc1[i][j][3] * DQS));
        }
    __syncthreads();
}

// per-key inverse norms over unit cols starting at word cbw, width W cols
__device__ __forceinline__ void norms(const ScanCtx& cx, int W, int cbw) {
    const int key = cx.t & 127, h = cx.t >> 7;
    const int cnt = W >> 2;
    const int wb = cbw + h * cnt;
    const uint32_t* base = (wb >= 64) ? (cx.smw + OF_KB + key * 68 + (wb - 64))
                                      : (cx.smw + OF_KA + key * 68 + wb);
    float s = 0.0f;
#pragma unroll 16
    for (int i = 0; i < cnt; ++i) {
        __half2 v = *(const __half2*)&base[i];
        float2 f = __half22float2(v);
        s += f.x * f.x + f.y * f.y;
    }
    cx.sm[OF_PART + cx.t] = s;
    __syncthreads();
    if (cx.t < 128) {
        float tot = cx.sm[OF_PART + cx.t] + cx.sm[OF_PART + cx.t + 128];
        cx.sm[OF_RN + cx.t] = 1.0f / fmaxf(sqrtf(tot), 1e-3f);
    }
    __syncthreads();
}

// GEMM2 (fp16): sims[256 q x 128 keys] = qhat_u @ Krot_u^T, then argmax resolve
__device__ __forceinline__ void g2_resolve(const ScanCtx& cx, int u, int d, int qoff, int cbw) {
    float acc2[4][8][4] = {};
    const int nch = d >> 5;  // >= 2 always
    stage_q(cx, qoff, 0); CPCOMMIT;
    stage_q(cx, qoff + 32, 1); CPCOMMIT;
    for (int kc = 0; kc < nch; ++kc) {
        if (kc < nch - 1) { CPWAIT1; } else { CPWAIT0; }
        __syncthreads();
        if (kc + 2 < nch) { stage_q(cx, qoff + (kc + 2) * 32, (kc + 2) % 3); CPCOMMIT; }
        const uint32_t baseQ = cx.sb4 + OF_STQ(kc % 3) * 4 + cx.offA2;
#pragma unroll
        for (int k16 = 0; k16 < 2; ++k16) {
            const int kw = kc * 16 + k16 * 8;
            uint32_t baseK;
            if (d == 256 && kw >= 64)
                baseK = cx.sb4 + OF_KB * 4 + (kw - 64) * 4 + cx.offB2;
            else
                baseK = cx.sb4 + OF_KA * 4 + (cbw + kw) * 4 + cx.offB2;
            uint32_t a[4][4];
#pragma unroll
            for (int i = 0; i < 4; ++i)
                ldsm4(a[i], baseQ + i * 1280 + k16 * 32);
            uint32_t bb[4][4];
#pragma unroll
            for (int jj = 0; jj < 4; ++jj)
                ldsm4(bb[jj], baseK + jj * 4352);  // 16 keys * 272B
#pragma unroll
            for (int jj = 0; jj < 4; ++jj)
#pragma unroll
                for (int i = 0; i < 4; ++i) {
                    mma16(acc2[i][2 * jj],     a[i], &bb[jj][0]);
                    mma16(acc2[i][2 * jj + 1], a[i], &bb[jj][2]);
                }
        }
    }
    // resolve
    float rk[8][2];
#pragma unroll
    for (int j = 0; j < 8; ++j) {
        const int kl = cx.n0g2 + 8 * j + (cx.lane & 3) * 2;
        rk[j][0] = cx.sm[OF_RN + kl];
        rk[j][1] = cx.sm[OF_RN + kl + 1];
    }
    unsigned long long* wmax = (unsigned long long*)(cx.sm + OF_WMAX);
#pragma unroll
    for (int i = 0; i < 4; ++i)
#pragma unroll
        for (int hh = 0; hh < 2; ++hh) {
            const int q = cx.m0g2 + 16 * i + (cx.lane >> 2) + 8 * hh;
            unsigned long long best = 0ULL;
#pragma unroll
            for (int j = 0; j < 8; ++j)
#pragma unroll
                for (int e = 0; e < 2; ++e) {
                    float v = acc2[i][j][hh * 2 + e] * rk[j][e];
                    unsigned uv = __float_as_uint(v);
                    uv = (uv & 0x80000000u) ? ~uv : (uv | 0x80000000u);
                    const int kg = cx.L0 + cx.n0g2 + 8 * j + (cx.lane & 3) * 2 + e;
                    unsigned long long pk = ((unsigned long long)uv << 32) |
                                            (unsigned long long)(0xFFFFFFFFu - (unsigned)kg);
                    best = umax64(best, pk);
                }
            best = umax64(best, __shfl_xor_sync(0xFFFFFFFFu, best, 1));
            best = umax64(best, __shfl_xor_sync(0xFFFFFFFFu, best, 2));
            if ((cx.lane & 3) == 0) wmax[q * 2 + (cx.w & 1)] = best;
        }
    __syncthreads();
    {
        unsigned long long m = umax64(wmax[cx.t * 2], wmax[cx.t * 2 + 1]);
        atomicMax(&g_best[u * BZd + cx.t], m);
    }
    __syncthreads();
}

__global__ void __launch_bounds__(256, 1) scan_kernel() {
    extern __shared__ float sm[];
    ScanCtx cx;
    cx.sm = sm;
    cx.smw = (uint32_t*)sm;
    cx.sb4 = (uint32_t)__cvta_generic_to_shared(sm);
    cx.t = threadIdx.x;
    cx.lane = cx.t & 31;
    cx.w = cx.t >> 5;
    cx.L0 = blockIdx.x * 128;
    cx.m0g1 = (cx.w >> 1) * 32;
    cx.n0g1 = (cx.w & 1) * 64;
    cx.m0g2 = (cx.w >> 1) * 64;
    cx.n0g2 = (cx.w & 1) * 64;
    {
        const int l = cx.lane;
        cx.offA1 = (uint32_t)((cx.m0g1 + (l & 7) + 8 * ((l >> 3) & 1)) * 80 + 16 * (l >> 4));
        cx.offA2 = (uint32_t)((cx.m0g2 + (l & 7) + 8 * ((l >> 3) & 1)) * 80 + 16 * (l >> 4));
        cx.offB1 = (uint32_t)((cx.n0g1 + (l & 7) + 8 * (l >> 4)) * 80 + 16 * ((l >> 3) & 1));
        cx.offB2 = (uint32_t)((cx.n0g2 + (l & 7) + 8 * (l >> 4)) * 272 + 16 * ((l >> 3) & 1));
    }

    // unit 0: cols 0..255
    g1_panel(cx, 0, OF_KA);
    g1_panel(cx, 1, OF_KB);
    norms(cx, 256, 0);
    g2_resolve(cx, 0, 256, 0, 0);
    // unit 1: cols 256..511
    g1_panel(cx, 2, OF_KA);
    g1_panel(cx, 3, OF_KB);
    norms(cx, 256, 0);
    g2_resolve(cx, 1, 256, 256, 0);
    // units 2..4: 128 cols each
    g1_panel(cx, 4, OF_KA);
    norms(cx, 128, 0);
    g2_resolve(cx, 2, 128, 512, 0);
    g1_panel(cx, 5, OF_KA);
    norms(cx, 128, 0);
    g2_resolve(cx, 3, 128, 640, 0);
    g1_panel(cx, 6, OF_KA);
    norms(cx, 128, 0);
    g2_resolve(cx, 4, 128, 768, 0);
    // units 5,6: 64 cols each, share panel 7
    g1_panel(cx, 7, OF_KA);
    norms(cx, 64, 0);
    g2_resolve(cx, 5, 64, 896, 0);
    norms(cx, 64, 32);
    g2_resolve(cx, 6, 64, 960, 32);
}

// ================= K3: exact fp32 cosine of winners =================
__global__ void final_kernel(const float* __restrict__ keys, const float* __restrict__ R) {
    __shared__ float sv[H];
    __shared__ float sred[256];
    const int u = blockIdx.x >> 8;
    const int b = blockIdx.x & 255;
    const int t = threadIdx.x;
    unsigned long long pk = g_best[u * BZd + b];
    unsigned idx = 0xFFFFFFFFu - (unsigned)(pk & 0xFFFFFFFFull);
    const float* v = keys + (size_t)idx * H;
    for (int i = t; i < H; i += 256) sv[i] = v[i];
    __syncthreads();
    const int d = c_ud[u], off = c_uoff[u];
    const int rep = 256 / d;
    const int ip = t / d;
    const int c = t - ip * d;
    const int chunk = H / rep;
    const int i0 = ip * chunk;
    float part = 0.0f;
    {
        const float* Rc = R + off + c;
#pragma unroll 4
        for (int i = i0; i < i0 + chunk; ++i) part += sv[i] * Rc[(size_t)i * H];
    }
    sred[t] = part;
    __syncthreads();
    float dg = 0.0f, qc = 0.0f;
    if (t < d) {
        dg = sred[t];
        for (int r = 1; r < rep; ++r) dg += sred[t + r * d];
        qc = g_qrot[(size_t)b * H + off + t];
    }
    __syncthreads();
    float vals[3] = {qc * dg, dg * dg, qc * qc};
    float tot[3];
#pragma unroll
    for (int r = 0; r < 3; ++r) {
        sred[t] = vals[r];
        __syncthreads();
        for (int w = 128; w > 0; w >>= 1) {
            if (t < w) sred[t] += sred[t + w];
            __syncthreads();
        }
        tot[r] = sred[0];
        __syncthreads();
    }
    if (t == 0) {
        float cosv = tot[0] / (fmaxf(sqrtf(tot[2]), 1e-8f) * fmaxf(sqrtf(tot[1]), 1e-8f));
        g_cos[u * BZd + b] = cosv * (float)d;
    }
}

// ================= K4: deterministic reduction =================
__global__ void reduce_kernel(float* __restrict__ out) {
    __shared__ float sred[256];
    const int t = threadIdx.x;
    float s = 0.0f;
    for (int k = t; k < NU * BZd; k += 256) s += g_cos[k];
    sred[t] = s;
    __syncthreads();
    for (int w = 128; w > 0; w >>= 1) {
        if (t < w) sred[t] += sred[t + w];
        __syncthreads();
    }
    if (t == 0) out[0] = -sred[0] / (float)(BZd * H);
}

// ================= launch =================
extern "C" void kernel_launch(void* const* d_in, const int* in_sizes, int n_in,
                              void* d_out, int out_size) {
    const float* query = nullptr;
    const float* keys = nullptr;
    const float* R = nullptr;
    for (int i = 0; i < n_in; ++i) {
        if (in_sizes[i] == BZd * H) query = (const float*)d_in[i];
        else if (in_sizes[i] == NKEYS * H) keys = (const float*)d_in[i];
        else if (in_sizes[i] == H * H) R = (const float*)d_in[i];
    }
    if (!query) query = (const float*)d_in[0];
    if (!keys) keys = (const float*)d_in[1];
    if (!R) R = (const float*)d_in[2];
    float* out = (float*)d_out;

    cudaFuncSetAttribute(scan_kernel, cudaFuncAttributeMaxDynamicSharedMemorySize, SMEM_BYTES);

    quant_keys<<<(int)((size_t)NKEYS * H / 4 / 256), 256>>>(keys);
    quant_Rt<<<dim3(32, 32), dim3(32, 8)>>>(R);
    qrot_kernel<<<128, 256>>>(query, R);
    qhat_kernel<<<256, 256>>>();
    scan_kernel<<<1024, 256, SMEM_BYTES>>>();
    final_kernel<<<NU * BZd, 256>>>(keys, R);
    reduce_kernel<<<1, 256>>>(out);
}